// round 1
// baseline (speedup 1.0000x reference)
#include <cuda_runtime.h>
#include <cuda_bf16.h>
#include <math.h>

// Problem constants
#define BB 4
#define NN 1024
#define DD 2048
#define HQ 16
#define HKV 4
#define DH 128
#define EE 3072           // (HQ + 2*HKV) * DH
#define MTOK 4096         // B*N

// ---------------- scratch (device globals; no allocation allowed) ----------
__device__ float g_qkv[MTOK * EE];               // 48 MB
__device__ float g_q[BB * HQ * NN * DH];         // 32 MB
__device__ float g_k[BB * HKV * NN * DH];        // 8 MB
__device__ float g_v[BB * HKV * NN * DH];        // 8 MB
__device__ float g_y[MTOK * DD];                 // 32 MB
__device__ float g_invfreq[64];

// ---------------------------------------------------------------------------
// inv_freq init (64 threads, double-precision pow for accuracy)
// ---------------------------------------------------------------------------
__global__ void init_invfreq_kernel() {
    int i = threadIdx.x;
    if (i < 64) {
        g_invfreq[i] = (float)pow(10000.0, -(double)(2 * i) / 128.0);
    }
}

// ---------------------------------------------------------------------------
// SGEMM:  C[M,Nc] = A[M,K] * B[Nc,K]^T      (both row-major, K contiguous)
// 128x128 tile, BK=16, 256 threads, 8x8 per-thread register tile.
// ---------------------------------------------------------------------------
__global__ __launch_bounds__(256)
void sgemm_nt_kernel(const float* __restrict__ A, const float* __restrict__ Bw,
                     float* __restrict__ C, int M, int Nc, int K) {
    __shared__ float As[16][132];   // [k][m], padded
    __shared__ float Bs[16][132];   // [k][n], padded

    int tid = threadIdx.x;
    int tx = tid & 15;
    int ty = tid >> 4;
    int m0 = blockIdx.y * 128;
    int n0 = blockIdx.x * 128;

    const float* Ab = A + (size_t)m0 * K;
    const float* Bb = Bw + (size_t)n0 * K;

    int lrow = tid >> 2;           // 0..63
    int lk4  = (tid & 3) * 4;      // 0,4,8,12

    float acc[8][8];
#pragma unroll
    for (int i = 0; i < 8; i++)
#pragma unroll
        for (int j = 0; j < 8; j++) acc[i][j] = 0.0f;

    for (int k0 = 0; k0 < K; k0 += 16) {
#pragma unroll
        for (int r = 0; r < 2; r++) {
            int row = lrow + r * 64;
            float4 va = *(const float4*)(Ab + (size_t)row * K + k0 + lk4);
            As[lk4 + 0][row] = va.x;
            As[lk4 + 1][row] = va.y;
            As[lk4 + 2][row] = va.z;
            As[lk4 + 3][row] = va.w;
            float4 vb = *(const float4*)(Bb + (size_t)row * K + k0 + lk4);
            Bs[lk4 + 0][row] = vb.x;
            Bs[lk4 + 1][row] = vb.y;
            Bs[lk4 + 2][row] = vb.z;
            Bs[lk4 + 3][row] = vb.w;
        }
        __syncthreads();

#pragma unroll
        for (int k = 0; k < 16; k++) {
            float a[8], b[8];
            *(float4*)(a)     = *(const float4*)&As[k][ty * 8];
            *(float4*)(a + 4) = *(const float4*)&As[k][ty * 8 + 4];
            *(float4*)(b)     = *(const float4*)&Bs[k][tx * 8];
            *(float4*)(b + 4) = *(const float4*)&Bs[k][tx * 8 + 4];
#pragma unroll
            for (int i = 0; i < 8; i++)
#pragma unroll
                for (int j = 0; j < 8; j++)
                    acc[i][j] = fmaf(a[i], b[j], acc[i][j]);
        }
        __syncthreads();
    }

#pragma unroll
    for (int i = 0; i < 8; i++) {
        size_t row = (size_t)(m0 + ty * 8 + i);
        float4 c0 = make_float4(acc[i][0], acc[i][1], acc[i][2], acc[i][3]);
        float4 c1 = make_float4(acc[i][4], acc[i][5], acc[i][6], acc[i][7]);
        *(float4*)(C + row * Nc + n0 + tx * 8)     = c0;
        *(float4*)(C + row * Nc + n0 + tx * 8 + 4) = c1;
    }
}

// ---------------------------------------------------------------------------
// RMSNorm + RoPE (+ V copy).  grid = (4096 tokens, 24 heads), 128 threads.
// ---------------------------------------------------------------------------
__global__ __launch_bounds__(128)
void normrope_kernel(const float* __restrict__ qkv, const int* __restrict__ pos,
                     const float* __restrict__ qw, const float* __restrict__ kw,
                     float* __restrict__ Q, float* __restrict__ K,
                     float* __restrict__ V) {
    int t = blockIdx.x;          // token 0..4095
    int hh = blockIdx.y;         // head 0..23
    int d = threadIdx.x;         // 0..127
    int b = t >> 10;
    int n = t & 1023;

    float v = qkv[(size_t)t * EE + hh * DH + d];

    if (hh >= HQ + HKV) {
        // V: plain copy
        V[(((size_t)(b * HKV + hh - (HQ + HKV)) * NN + n) * DH) + d] = v;
        return;
    }

    __shared__ float s[128];
    __shared__ float red[4];

    float sq = v * v;
#pragma unroll
    for (int o = 16; o > 0; o >>= 1) sq += __shfl_xor_sync(0xFFFFFFFFu, sq, o);
    if ((d & 31) == 0) red[d >> 5] = sq;
    __syncthreads();
    float ms = (red[0] + red[1] + red[2] + red[3]) * (1.0f / 128.0f);
    float r = rsqrtf(ms + 1.1920929e-7f);
    float w = (hh < HQ) ? qw[d] : kw[d];
    s[d] = v * r * w;
    __syncthreads();

    float p = (float)pos[n];
    int f = (d < 64) ? d : d - 64;
    float ang = p * g_invfreq[f];
    float c, sn;
    sincosf(ang, &sn, &c);
    float out;
    if (d < 64) out = s[d] * c - s[d + 64] * sn;
    else        out = s[d] * c + s[d - 64] * sn;

    if (hh < HQ)
        Q[(((size_t)(b * HQ + hh) * NN + n) * DH) + d] = out;
    else
        K[(((size_t)(b * HKV + hh - HQ) * NN + n) * DH) + d] = out;
}

// ---------------------------------------------------------------------------
// Flash attention (fp32), causal.  64 queries x 64 keys per tile, 256 threads.
// K and V share one smem buffer (sequential use).  Scale folded into Q load.
// ---------------------------------------------------------------------------
struct AttnSmem {
    float Qs[64][132];
    float KVs[64][132];
    float Ps[64][65];
    float row_alpha[64];
    float row_l[64];
};

__global__ __launch_bounds__(256)
void attn_kernel(const float* __restrict__ Qg, const float* __restrict__ Kg,
                 const float* __restrict__ Vg, float* __restrict__ Y) {
    extern __shared__ char smraw[];
    AttnSmem& sm = *(AttnSmem*)smraw;

    const int tid = threadIdx.x;
    const int qt = blockIdx.x;   // query tile 0..15
    const int h  = blockIdx.y;   // 0..15
    const int b  = blockIdx.z;   // 0..3
    const int q0 = qt * 64;
    const int hk = h >> 2;

    const float* Qp = Qg + (((size_t)(b * HQ + h) * NN + q0) * DH);
    const float* Kp = Kg + (((size_t)(b * HKV + hk) * NN) * DH);
    const float* Vp = Vg + (((size_t)(b * HKV + hk) * NN) * DH);

    const float scale = 0.08838834764831845f;  // 128^-0.5

    // Load Q tile (scaled): 64x128 = 2048 float4, 8 per thread
#pragma unroll
    for (int i = 0; i < 8; i++) {
        int idx = tid + i * 256;
        int row = idx >> 5;
        int c4  = idx & 31;
        float4 v = *(const float4*)(Qp + (size_t)row * DH + c4 * 4);
        v.x *= scale; v.y *= scale; v.z *= scale; v.w *= scale;
        *(float4*)&sm.Qs[row][c4 * 4] = v;
    }

    const int tx = tid & 15;
    const int ty = tid >> 4;
    const int qg = tid >> 5;   // 0..7  (query group of 8 for PV/output)
    const int dg = tid & 31;   // 0..31 (dim group of 4)

    float m_run = -1.0e30f, l_run = 0.0f;  // valid on tid<64
    float o[8][4];
#pragma unroll
    for (int i = 0; i < 8; i++)
#pragma unroll
        for (int c = 0; c < 4; c++) o[i][c] = 0.0f;

    for (int kt = 0; kt <= qt; kt++) {
        // ---- load K tile into KVs
        __syncthreads();  // protect KVs + Ps from previous iteration readers
        const float* Kt = Kp + (size_t)kt * 64 * DH;
#pragma unroll
        for (int i = 0; i < 8; i++) {
            int idx = tid + i * 256;
            int row = idx >> 5;
            int c4  = idx & 31;
            *(float4*)&sm.KVs[row][c4 * 4] = *(const float4*)(Kt + (size_t)row * DH + c4 * 4);
        }
        __syncthreads();

        // ---- S = Q K^T  (thread computes rows ty*4+i, key cols tx+16*j)
        float s[4][4];
#pragma unroll
        for (int i = 0; i < 4; i++)
#pragma unroll
            for (int j = 0; j < 4; j++) s[i][j] = 0.0f;

#pragma unroll 8
        for (int c4 = 0; c4 < 32; c4++) {
            float4 qv[4], kv[4];
#pragma unroll
            for (int i = 0; i < 4; i++) qv[i] = *(const float4*)&sm.Qs[ty * 4 + i][c4 * 4];
#pragma unroll
            for (int j = 0; j < 4; j++) kv[j] = *(const float4*)&sm.KVs[tx + 16 * j][c4 * 4];
#pragma unroll
            for (int i = 0; i < 4; i++)
#pragma unroll
                for (int j = 0; j < 4; j++) {
                    s[i][j] = fmaf(qv[i].x, kv[j].x, s[i][j]);
                    s[i][j] = fmaf(qv[i].y, kv[j].y, s[i][j]);
                    s[i][j] = fmaf(qv[i].z, kv[j].z, s[i][j]);
                    s[i][j] = fmaf(qv[i].w, kv[j].w, s[i][j]);
                }
        }

        // causal mask on diagonal tile
        if (kt == qt) {
#pragma unroll
            for (int i = 0; i < 4; i++)
#pragma unroll
                for (int j = 0; j < 4; j++) {
                    if (tx + 16 * j > ty * 4 + i) s[i][j] = -1.0e30f;
                }
        }

#pragma unroll
        for (int i = 0; i < 4; i++)
#pragma unroll
            for (int j = 0; j < 4; j++)
                sm.Ps[ty * 4 + i][tx + 16 * j] = s[i][j];
        __syncthreads();

        // ---- online softmax on rows (threads 0..63), V load (all threads)
        if (tid < 64) {
            int rr = tid;
            float tmax = -1.0e30f;
#pragma unroll 8
            for (int j = 0; j < 64; j++) tmax = fmaxf(tmax, sm.Ps[rr][j]);
            float mnew = fmaxf(m_run, tmax);
            float alpha = __expf(m_run - mnew);
            float l = l_run * alpha;
#pragma unroll 8
            for (int j = 0; j < 64; j++) {
                float pv = __expf(sm.Ps[rr][j] - mnew);
                sm.Ps[rr][j] = pv;
                l += pv;
            }
            m_run = mnew;
            l_run = l;
            sm.row_alpha[rr] = alpha;
        }
        // V tile load (reuses KVs; all prior K readers passed the sync above)
        const float* Vt = Vp + (size_t)kt * 64 * DH;
#pragma unroll
        for (int i = 0; i < 8; i++) {
            int idx = tid + i * 256;
            int row = idx >> 5;
            int c4  = idx & 31;
            *(float4*)&sm.KVs[row][c4 * 4] = *(const float4*)(Vt + (size_t)row * DH + c4 * 4);
        }
        __syncthreads();

        // ---- rescale O, then O += P * V
#pragma unroll
        for (int i = 0; i < 8; i++) {
            float a = sm.row_alpha[qg * 8 + i];
#pragma unroll
            for (int c = 0; c < 4; c++) o[i][c] *= a;
        }
#pragma unroll 4
        for (int j = 0; j < 64; j++) {
            float4 vv = *(const float4*)&sm.KVs[j][dg * 4];
#pragma unroll
            for (int i = 0; i < 8; i++) {
                float pp = sm.Ps[qg * 8 + i][j];
                o[i][0] = fmaf(pp, vv.x, o[i][0]);
                o[i][1] = fmaf(pp, vv.y, o[i][1]);
                o[i][2] = fmaf(pp, vv.z, o[i][2]);
                o[i][3] = fmaf(pp, vv.w, o[i][3]);
            }
        }
    }

    __syncthreads();
    if (tid < 64) sm.row_l[tid] = l_run;
    __syncthreads();

    // write Y[b][n][h*128 + d]
#pragma unroll
    for (int i = 0; i < 8; i++) {
        int q = qg * 8 + i;
        float inv = 1.0f / sm.row_l[q];
        float4 out = make_float4(o[i][0] * inv, o[i][1] * inv, o[i][2] * inv, o[i][3] * inv);
        *(float4*)(Y + ((size_t)(b * NN + q0 + q)) * DD + h * DH + dg * 4) = out;
    }
}

// ---------------------------------------------------------------------------
// launch
// ---------------------------------------------------------------------------
extern "C" void kernel_launch(void* const* d_in, const int* in_sizes, int n_in,
                              void* d_out, int out_size) {
    const float* x     = (const float*)d_in[0];
    // d_in[1] = mask (causal triu, deterministic -> unused)
    const int*   pos   = (const int*)d_in[2];
    const float* w_qkv = (const float*)d_in[3];
    const float* w_out = (const float*)d_in[4];
    const float* qw    = (const float*)d_in[5];
    const float* kw    = (const float*)d_in[6];
    float* out = (float*)d_out;

    float *qkv, *q, *k, *v, *y;
    cudaGetSymbolAddress((void**)&qkv, g_qkv);
    cudaGetSymbolAddress((void**)&q,   g_q);
    cudaGetSymbolAddress((void**)&k,   g_k);
    cudaGetSymbolAddress((void**)&v,   g_v);
    cudaGetSymbolAddress((void**)&y,   g_y);

    init_invfreq_kernel<<<1, 64>>>();

    // QKV GEMM: [4096,2048] x [3072,2048]^T
    sgemm_nt_kernel<<<dim3(EE / 128, MTOK / 128), 256>>>(x, w_qkv, qkv, MTOK, EE, DD);

    // RMSNorm + RoPE + split
    normrope_kernel<<<dim3(MTOK, HQ + 2 * HKV), 128>>>(qkv, pos, qw, kw, q, k, v);

    // Attention
    cudaFuncSetAttribute(attn_kernel, cudaFuncAttributeMaxDynamicSharedMemorySize,
                         (int)sizeof(AttnSmem));
    attn_kernel<<<dim3(NN / 64, HQ, BB), 256, sizeof(AttnSmem)>>>(q, k, v, y);

    // Output GEMM: [4096,2048] x [2048,2048]^T
    sgemm_nt_kernel<<<dim3(DD / 128, MTOK / 128), 256>>>(y, w_out, out, MTOK, DD, DD);
}

// round 6
// speedup vs baseline: 1.7315x; 1.7315x over previous
#include <cuda_runtime.h>
#include <cuda_bf16.h>
#include <math.h>
#include <stdint.h>

// Problem constants
#define BB 4
#define NN 1024
#define DD 2048
#define HQ 16
#define HKV 4
#define DH 128
#define EE 3072           // (HQ + 2*HKV) * DH
#define MTOK 4096         // B*N

// ---------------- scratch (device globals; no allocation allowed) ----------
__device__ float g_qkv[MTOK * EE];
__device__ float g_q[BB * HQ * NN * DH];
__device__ float g_k[BB * HKV * NN * DH];
__device__ float g_v[BB * HKV * NN * DH];
__device__ float g_y[MTOK * DD];
__device__ float g_invfreq[64];

// bf16 split operands
__device__ __nv_bfloat16 g_xh[MTOK * DD],  g_xl[MTOK * DD];
__device__ __nv_bfloat16 g_wqh[EE * DD],   g_wql[EE * DD];
__device__ __nv_bfloat16 g_woh[DD * DD],   g_wol[DD * DD];
__device__ __nv_bfloat16 g_yh[MTOK * DD],  g_yl[MTOK * DD];

// ---------------------------------------------------------------------------
// portable PTX helpers (valid on plain sm_103 target)
// ---------------------------------------------------------------------------
__device__ __forceinline__ uint32_t smem_u32_of(const void* p) {
    uint32_t a;
    asm("{ .reg .u64 t; cvta.to.shared.u64 t, %1; cvt.u32.u64 %0, t; }"
        : "=r"(a) : "l"(p));
    return a;
}
#define CP_ASYNC16(dst, src) \
    asm volatile("cp.async.cg.shared.global [%0], [%1], 16;" :: "r"(dst), "l"(src))
#define CP_COMMIT() asm volatile("cp.async.commit_group;" ::: "memory")
#define CP_WAIT2()  asm volatile("cp.async.wait_group 2;" ::: "memory")

__device__ __forceinline__ void ldm_x4(uint32_t* r, uint32_t addr) {
    asm volatile("ldmatrix.sync.aligned.m8n8.x4.shared.b16 {%0,%1,%2,%3}, [%4];"
                 : "=r"(r[0]), "=r"(r[1]), "=r"(r[2]), "=r"(r[3]) : "r"(addr));
}
__device__ __forceinline__ void ldm_x2(uint32_t* r, uint32_t addr) {
    asm volatile("ldmatrix.sync.aligned.m8n8.x2.shared.b16 {%0,%1}, [%2];"
                 : "=r"(r[0]), "=r"(r[1]) : "r"(addr));
}
__device__ __forceinline__ void mma_bf16(float* c, const uint32_t* a, const uint32_t* b) {
    asm volatile(
        "mma.sync.aligned.m16n8k16.row.col.f32.bf16.bf16.f32 "
        "{%0,%1,%2,%3}, {%4,%5,%6,%7}, {%8,%9}, {%0,%1,%2,%3};"
        : "+f"(c[0]), "+f"(c[1]), "+f"(c[2]), "+f"(c[3])
        : "r"(a[0]), "r"(a[1]), "r"(a[2]), "r"(a[3]), "r"(b[0]), "r"(b[1]));
}

// ---------------------------------------------------------------------------
// inv_freq init
// ---------------------------------------------------------------------------
__global__ void init_invfreq_kernel() {
    int i = threadIdx.x;
    if (i < 64) g_invfreq[i] = (float)pow(10000.0, -(double)(2 * i) / 128.0);
}

// ---------------------------------------------------------------------------
// fp32 -> (bf16 hi, bf16 lo) split, float4-vectorized
// ---------------------------------------------------------------------------
__global__ __launch_bounds__(256)
void split_bf16_kernel(const float* __restrict__ s, __nv_bfloat16* __restrict__ hi,
                       __nv_bfloat16* __restrict__ lo, int n4) {
    int i = blockIdx.x * blockDim.x + threadIdx.x;
    if (i >= n4) return;
    float4 v = ((const float4*)s)[i];
    __nv_bfloat16 h0 = __float2bfloat16(v.x);
    __nv_bfloat16 h1 = __float2bfloat16(v.y);
    __nv_bfloat16 h2 = __float2bfloat16(v.z);
    __nv_bfloat16 h3 = __float2bfloat16(v.w);
    __nv_bfloat16 l0 = __float2bfloat16(v.x - __bfloat162float(h0));
    __nv_bfloat16 l1 = __float2bfloat16(v.y - __bfloat162float(h1));
    __nv_bfloat16 l2 = __float2bfloat16(v.z - __bfloat162float(h2));
    __nv_bfloat16 l3 = __float2bfloat16(v.w - __bfloat162float(h3));
    uint2 hp, lp;
    hp.x = (uint32_t)__bfloat16_as_ushort(h0) | ((uint32_t)__bfloat16_as_ushort(h1) << 16);
    hp.y = (uint32_t)__bfloat16_as_ushort(h2) | ((uint32_t)__bfloat16_as_ushort(h3) << 16);
    lp.x = (uint32_t)__bfloat16_as_ushort(l0) | ((uint32_t)__bfloat16_as_ushort(l1) << 16);
    lp.y = (uint32_t)__bfloat16_as_ushort(l2) | ((uint32_t)__bfloat16_as_ushort(l3) << 16);
    ((uint2*)hi)[i] = hp;
    ((uint2*)lo)[i] = lp;
}

// ---------------------------------------------------------------------------
// mma.sync split-bf16 GEMM:
//   C[M,Nc] = (Ahi+Alo)[M,K] * (Bhi+Blo)[Nc,K]^T  via 3 bf16 products
// 128x128 CTA tile, K-chunk 32, 3-stage cp.async pipeline.
// smem tiles: 128 rows x 32 bf16, padded row stride 40 bf16 (80 B).
// ---------------------------------------------------------------------------
#define GSTRIDE 40                         // bf16 elements per smem row
#define TILE_BYTES (128 * GSTRIDE * 2)     // 10240
#define STAGE_BYTES (4 * TILE_BYTES)       // Ahi, Alo, Bhi, Blo = 40960
#define NSTAGE 3

__global__ __launch_bounds__(256, 1)
void mma_gemm3_kernel(const __nv_bfloat16* __restrict__ Ahi, const __nv_bfloat16* __restrict__ Alo,
                      const __nv_bfloat16* __restrict__ Bhi, const __nv_bfloat16* __restrict__ Blo,
                      float* __restrict__ C, int Nc, int K) {
    extern __shared__ char smem[];
    const uint32_t smem_b = smem_u32_of(smem);

    const int tid = threadIdx.x;
    const int wid = tid >> 5;
    const int lane = tid & 31;
    const int warp_m = wid & 1;        // 0..1  (64 rows each)
    const int warp_n = wid >> 1;       // 0..3  (32 cols each)
    const int m0 = blockIdx.y * 128;
    const int n0 = blockIdx.x * 128;

    const int NCH = K >> 5;            // chunks of 32

    // ---- stage loader: 2048 16B chunks / 256 threads = 8 per thread
    auto load_stage = [&](int st, int kc) {
        const uint32_t sb = smem_b + st * STAGE_BYTES;
        const int k0 = kc * 32;
#pragma unroll
        for (int t = 0; t < 8; t++) {
            int idx = tid + t * 256;           // 0..2047
            int tile = idx >> 9;               // 0..3
            int w = idx & 511;
            int r = w >> 2;                    // 0..127
            int c = w & 3;                     // 16B chunk
            const __nv_bfloat16* base =
                (tile == 0) ? Ahi : (tile == 1) ? Alo : (tile == 2) ? Bhi : Blo;
            int row0 = (tile < 2) ? m0 : n0;
            const __nv_bfloat16* src = base + (size_t)(row0 + r) * K + k0 + c * 8;
            uint32_t dst = sb + tile * TILE_BYTES + r * (GSTRIDE * 2) + c * 16;
            CP_ASYNC16(dst, src);
        }
        CP_COMMIT();
    };

    float acc[4][4][4];
#pragma unroll
    for (int i = 0; i < 4; i++)
#pragma unroll
        for (int j = 0; j < 4; j++)
#pragma unroll
            for (int k = 0; k < 4; k++) acc[i][j][k] = 0.0f;

    // prologue: chunks 0,1
    load_stage(0, 0);
    load_stage(1, 1);

    // ldmatrix base offsets for this thread (within a tile)
    // A frags: row = warp_m*64 + mi*16 + (lane&15), col = kk + (lane>>4)*8
    const int a_row = warp_m * 64 + (lane & 15);
    const int a_cb  = (lane >> 4) * 8;
    // B frags: row = warp_n*32 + ni*8 + (lane&7), col = kk + ((lane>>3)&1)*8
    const int b_row = warp_n * 32 + (lane & 7);
    const int b_cb  = ((lane >> 3) & 1) * 8;

    for (int cch = 0; cch < NCH; cch++) {
        int buf = cch % NSTAGE;
        if (cch + 2 < NCH) load_stage((cch + 2) % NSTAGE, cch + 2);
        else CP_COMMIT();                 // keep group count uniform
        CP_WAIT2();
        __syncthreads();

        const uint32_t sb = smem_b + buf * STAGE_BYTES;
        const uint32_t sAh = sb;
        const uint32_t sAl = sb + TILE_BYTES;
        const uint32_t sBh = sb + 2 * TILE_BYTES;
        const uint32_t sBl = sb + 3 * TILE_BYTES;

#pragma unroll
        for (int ks = 0; ks < 2; ks++) {
            const int kk = ks * 16;
            uint32_t ah[4][4], al[4][4], bh[4][2], bl[4][2];
#pragma unroll
            for (int mi = 0; mi < 4; mi++) {
                uint32_t off = (uint32_t)((a_row + mi * 16) * (GSTRIDE * 2) + (kk + a_cb) * 2);
                ldm_x4(ah[mi], sAh + off);
                ldm_x4(al[mi], sAl + off);
            }
#pragma unroll
            for (int ni = 0; ni < 4; ni++) {
                uint32_t off = (uint32_t)((b_row + ni * 8) * (GSTRIDE * 2) + (kk + b_cb) * 2);
                ldm_x2(bh[ni], sBh + off);
                ldm_x2(bl[ni], sBl + off);
            }
#pragma unroll
            for (int mi = 0; mi < 4; mi++)
#pragma unroll
                for (int ni = 0; ni < 4; ni++) {
                    mma_bf16(acc[mi][ni], ah[mi], bh[ni]);   // hi*hi
                    mma_bf16(acc[mi][ni], ah[mi], bl[ni]);   // hi*lo
                    mma_bf16(acc[mi][ni], al[mi], bh[ni]);   // lo*hi
                }
        }
        __syncthreads();
    }

    // ---- epilogue: D layout m16n8 -> rows lane/4 (+8), cols 2*(lane%4)+{0,1}
    const int er = lane >> 2;
    const int ec = (lane & 3) * 2;
#pragma unroll
    for (int mi = 0; mi < 4; mi++) {
#pragma unroll
        for (int ni = 0; ni < 4; ni++) {
            int gm = m0 + warp_m * 64 + mi * 16 + er;
            int gn = n0 + warp_n * 32 + ni * 8 + ec;
            *(float2*)(C + (size_t)gm * Nc + gn) = make_float2(acc[mi][ni][0], acc[mi][ni][1]);
            *(float2*)(C + (size_t)(gm + 8) * Nc + gn) = make_float2(acc[mi][ni][2], acc[mi][ni][3]);
        }
    }
}

// ---------------------------------------------------------------------------
// RMSNorm + RoPE (+ V copy).  grid = (4096 tokens, 24 heads), 128 threads.
// ---------------------------------------------------------------------------
__global__ __launch_bounds__(128)
void normrope_kernel(const float* __restrict__ qkv, const int* __restrict__ pos,
                     const float* __restrict__ qw, const float* __restrict__ kw,
                     float* __restrict__ Q, float* __restrict__ K,
                     float* __restrict__ V) {
    int t = blockIdx.x;
    int hh = blockIdx.y;
    int d = threadIdx.x;
    int b = t >> 10;
    int n = t & 1023;

    float v = qkv[(size_t)t * EE + hh * DH + d];

    if (hh >= HQ + HKV) {
        V[(((size_t)(b * HKV + hh - (HQ + HKV)) * NN + n) * DH) + d] = v;
        return;
    }

    __shared__ float s[128];
    __shared__ float red[4];

    float sq = v * v;
#pragma unroll
    for (int o = 16; o > 0; o >>= 1) sq += __shfl_xor_sync(0xFFFFFFFFu, sq, o);
    if ((d & 31) == 0) red[d >> 5] = sq;
    __syncthreads();
    float ms = (red[0] + red[1] + red[2] + red[3]) * (1.0f / 128.0f);
    float r = rsqrtf(ms + 1.1920929e-7f);
    float w = (hh < HQ) ? qw[d] : kw[d];
    s[d] = v * r * w;
    __syncthreads();

    float p = (float)pos[n];
    int f = (d < 64) ? d : d - 64;
    float ang = p * g_invfreq[f];
    float c, sn;
    sincosf(ang, &sn, &c);
    float out;
    if (d < 64) out = s[d] * c - s[d + 64] * sn;
    else        out = s[d] * c + s[d - 64] * sn;

    if (hh < HQ)
        Q[(((size_t)(b * HQ + hh) * NN + n) * DH) + d] = out;
    else
        K[(((size_t)(b * HKV + hh - HQ) * NN + n) * DH) + d] = out;
}

// ---------------------------------------------------------------------------
// Flash attention (fp32), causal.  64x64 tiles, 256 threads.  (unchanged, R1)
// ---------------------------------------------------------------------------
struct AttnSmem {
    float Qs[64][132];
    float KVs[64][132];
    float Ps[64][65];
    float row_alpha[64];
    float row_l[64];
};

__global__ __launch_bounds__(256)
void attn_kernel(const float* __restrict__ Qg, const float* __restrict__ Kg,
                 const float* __restrict__ Vg, float* __restrict__ Y) {
    extern __shared__ char smraw[];
    AttnSmem& sm = *(AttnSmem*)smraw;

    const int tid = threadIdx.x;
    const int qt = blockIdx.x;
    const int h  = blockIdx.y;
    const int b  = blockIdx.z;
    const int q0 = qt * 64;
    const int hk = h >> 2;

    const float* Qp = Qg + (((size_t)(b * HQ + h) * NN + q0) * DH);
    const float* Kp = Kg + (((size_t)(b * HKV + hk) * NN) * DH);
    const float* Vp = Vg + (((size_t)(b * HKV + hk) * NN) * DH);

    const float scale = 0.08838834764831845f;

#pragma unroll
    for (int i = 0; i < 8; i++) {
        int idx = tid + i * 256;
        int row = idx >> 5;
        int c4  = idx & 31;
        float4 v = *(const float4*)(Qp + (size_t)row * DH + c4 * 4);
        v.x *= scale; v.y *= scale; v.z *= scale; v.w *= scale;
        *(float4*)&sm.Qs[row][c4 * 4] = v;
    }

    const int tx = tid & 15;
    const int ty = tid >> 4;
    const int qg = tid >> 5;
    const int dg = tid & 31;

    float m_run = -1.0e30f, l_run = 0.0f;
    float o[8][4];
#pragma unroll
    for (int i = 0; i < 8; i++)
#pragma unroll
        for (int c = 0; c < 4; c++) o[i][c] = 0.0f;

    for (int kt = 0; kt <= qt; kt++) {
        __syncthreads();
        const float* Kt = Kp + (size_t)kt * 64 * DH;
#pragma unroll
        for (int i = 0; i < 8; i++) {
            int idx = tid + i * 256;
            int row = idx >> 5;
            int c4  = idx & 31;
            *(float4*)&sm.KVs[row][c4 * 4] = *(const float4*)(Kt + (size_t)row * DH + c4 * 4);
        }
        __syncthreads();

        float s[4][4];
#pragma unroll
        for (int i = 0; i < 4; i++)
#pragma unroll
            for (int j = 0; j < 4; j++) s[i][j] = 0.0f;

#pragma unroll 8
        for (int c4 = 0; c4 < 32; c4++) {
            float4 qv[4], kv[4];
#pragma unroll
            for (int i = 0; i < 4; i++) qv[i] = *(const float4*)&sm.Qs[ty * 4 + i][c4 * 4];
#pragma unroll
            for (int j = 0; j < 4; j++) kv[j] = *(const float4*)&sm.KVs[tx + 16 * j][c4 * 4];
#pragma unroll
            for (int i = 0; i < 4; i++)
#pragma unroll
                for (int j = 0; j < 4; j++) {
                    s[i][j] = fmaf(qv[i].x, kv[j].x, s[i][j]);
                    s[i][j] = fmaf(qv[i].y, kv[j].y, s[i][j]);
                    s[i][j] = fmaf(qv[i].z, kv[j].z, s[i][j]);
                    s[i][j] = fmaf(qv[i].w, kv[j].w, s[i][j]);
                }
        }

        if (kt == qt) {
#pragma unroll
            for (int i = 0; i < 4; i++)
#pragma unroll
                for (int j = 0; j < 4; j++)
                    if (tx + 16 * j > ty * 4 + i) s[i][j] = -1.0e30f;
        }

#pragma unroll
        for (int i = 0; i < 4; i++)
#pragma unroll
            for (int j = 0; j < 4; j++)
                sm.Ps[ty * 4 + i][tx + 16 * j] = s[i][j];
        __syncthreads();

        if (tid < 64) {
            int rr = tid;
            float tmax = -1.0e30f;
#pragma unroll 8
            for (int j = 0; j < 64; j++) tmax = fmaxf(tmax, sm.Ps[rr][j]);
            float mnew = fmaxf(m_run, tmax);
            float alpha = __expf(m_run - mnew);
            float l = l_run * alpha;
#pragma unroll 8
            for (int j = 0; j < 64; j++) {
                float pv = __expf(sm.Ps[rr][j] - mnew);
                sm.Ps[rr][j] = pv;
                l += pv;
            }
            m_run = mnew;
            l_run = l;
            sm.row_alpha[rr] = alpha;
        }
        const float* Vt = Vp + (size_t)kt * 64 * DH;
#pragma unroll
        for (int i = 0; i < 8; i++) {
            int idx = tid + i * 256;
            int row = idx >> 5;
            int c4  = idx & 31;
            *(float4*)&sm.KVs[row][c4 * 4] = *(const float4*)(Vt + (size_t)row * DH + c4 * 4);
        }
        __syncthreads();

#pragma unroll
        for (int i = 0; i < 8; i++) {
            float a = sm.row_alpha[qg * 8 + i];
#pragma unroll
            for (int c = 0; c < 4; c++) o[i][c] *= a;
        }
#pragma unroll 4
        for (int j = 0; j < 64; j++) {
            float4 vv = *(const float4*)&sm.KVs[j][dg * 4];
#pragma unroll
            for (int i = 0; i < 8; i++) {
                float pp = sm.Ps[qg * 8 + i][j];
                o[i][0] = fmaf(pp, vv.x, o[i][0]);
                o[i][1] = fmaf(pp, vv.y, o[i][1]);
                o[i][2] = fmaf(pp, vv.z, o[i][2]);
                o[i][3] = fmaf(pp, vv.w, o[i][3]);
            }
        }
    }

    __syncthreads();
    if (tid < 64) sm.row_l[tid] = l_run;
    __syncthreads();

#pragma unroll
    for (int i = 0; i < 8; i++) {
        int q = qg * 8 + i;
        float inv = 1.0f / sm.row_l[q];
        float4 out = make_float4(o[i][0] * inv, o[i][1] * inv, o[i][2] * inv, o[i][3] * inv);
        *(float4*)(Y + ((size_t)(b * NN + q0 + q)) * DD + h * DH + dg * 4) = out;
    }
}

// ---------------------------------------------------------------------------
// launch
// ---------------------------------------------------------------------------
extern "C" void kernel_launch(void* const* d_in, const int* in_sizes, int n_in,
                              void* d_out, int out_size) {
    const float* x     = (const float*)d_in[0];
    const int*   pos   = (const int*)d_in[2];
    const float* w_qkv = (const float*)d_in[3];
    const float* w_out = (const float*)d_in[4];
    const float* qw    = (const float*)d_in[5];
    const float* kw    = (const float*)d_in[6];
    float* out = (float*)d_out;

    float *qkv, *q, *k, *v, *y;
    cudaGetSymbolAddress((void**)&qkv, g_qkv);
    cudaGetSymbolAddress((void**)&q,   g_q);
    cudaGetSymbolAddress((void**)&k,   g_k);
    cudaGetSymbolAddress((void**)&v,   g_v);
    cudaGetSymbolAddress((void**)&y,   g_y);

    __nv_bfloat16 *xh, *xl, *wqh, *wql, *woh, *wol, *yh, *yl;
    cudaGetSymbolAddress((void**)&xh,  g_xh);
    cudaGetSymbolAddress((void**)&xl,  g_xl);
    cudaGetSymbolAddress((void**)&wqh, g_wqh);
    cudaGetSymbolAddress((void**)&wql, g_wql);
    cudaGetSymbolAddress((void**)&woh, g_woh);
    cudaGetSymbolAddress((void**)&wol, g_wol);
    cudaGetSymbolAddress((void**)&yh,  g_yh);
    cudaGetSymbolAddress((void**)&yl,  g_yl);

    cudaFuncSetAttribute(mma_gemm3_kernel, cudaFuncAttributeMaxDynamicSharedMemorySize,
                         NSTAGE * STAGE_BYTES);
    cudaFuncSetAttribute(attn_kernel, cudaFuncAttributeMaxDynamicSharedMemorySize,
                         (int)sizeof(AttnSmem));

    init_invfreq_kernel<<<1, 64>>>();

    // split x and w_qkv to bf16 hi/lo
    split_bf16_kernel<<<(MTOK * DD / 4 + 255) / 256, 256>>>(x, xh, xl, MTOK * DD / 4);
    split_bf16_kernel<<<(EE * DD / 4 + 255) / 256, 256>>>(w_qkv, wqh, wql, EE * DD / 4);

    // QKV GEMM: [4096,2048] x [3072,2048]^T  (mma.sync bf16, 3-product split)
    mma_gemm3_kernel<<<dim3(EE / 128, MTOK / 128), 256, NSTAGE * STAGE_BYTES>>>(
        xh, xl, wqh, wql, qkv, EE, DD);

    // RMSNorm + RoPE + split
    normrope_kernel<<<dim3(MTOK, HQ + 2 * HKV), 128>>>(qkv, pos, qw, kw, q, k, v);

    // Attention (SIMT fp32 flash)
    attn_kernel<<<dim3(NN / 64, HQ, BB), 256, sizeof(AttnSmem)>>>(q, k, v, y);

    // split y and w_out, then output GEMM
    split_bf16_kernel<<<(MTOK * DD / 4 + 255) / 256, 256>>>(y, yh, yl, MTOK * DD / 4);
    split_bf16_kernel<<<(DD * DD / 4 + 255) / 256, 256>>>(w_out, woh, wol, DD * DD / 4);

    mma_gemm3_kernel<<<dim3(DD / 128, MTOK / 128), 256, NSTAGE * STAGE_BYTES>>>(
        yh, yl, woh, wol, out, DD, DD);
}

// round 7
// speedup vs baseline: 2.1141x; 1.2210x over previous
#include <cuda_runtime.h>
#include <cuda_bf16.h>
#include <math.h>
#include <stdint.h>

// Problem constants
#define BB 4
#define NN 1024
#define DD 2048
#define HQ 16
#define HKV 4
#define DH 128
#define EE 3072           // (HQ + 2*HKV) * DH
#define MTOK 4096         // B*N

// ---------------- scratch (device globals; no allocation allowed) ----------
__device__ float g_qkv[MTOK * EE];
__device__ float g_invfreq[64];

// bf16 split operands
__device__ __nv_bfloat16 g_xh[MTOK * DD],  g_xl[MTOK * DD];
__device__ __nv_bfloat16 g_wqh[EE * DD],   g_wql[EE * DD];
__device__ __nv_bfloat16 g_woh[DD * DD],   g_wol[DD * DD];
__device__ __nv_bfloat16 g_yh[MTOK * DD],  g_yl[MTOK * DD];
// attention operands (bf16 hi/lo, Q pre-scaled)
__device__ __nv_bfloat16 g_qh[BB * HQ * NN * DH],  g_ql[BB * HQ * NN * DH];
__device__ __nv_bfloat16 g_kh[BB * HKV * NN * DH], g_kl[BB * HKV * NN * DH];
__device__ __nv_bfloat16 g_vh[BB * HKV * NN * DH], g_vl[BB * HKV * NN * DH];

// ---------------------------------------------------------------------------
// portable PTX helpers (valid on plain sm_103 target)
// ---------------------------------------------------------------------------
__device__ __forceinline__ uint32_t smem_u32_of(const void* p) {
    uint32_t a;
    asm("{ .reg .u64 t; cvta.to.shared.u64 t, %1; cvt.u32.u64 %0, t; }"
        : "=r"(a) : "l"(p));
    return a;
}
#define CP_ASYNC16(dst, src) \
    asm volatile("cp.async.cg.shared.global [%0], [%1], 16;" :: "r"(dst), "l"(src))
#define CP_COMMIT() asm volatile("cp.async.commit_group;" ::: "memory")
#define CP_WAIT2()  asm volatile("cp.async.wait_group 2;" ::: "memory")

__device__ __forceinline__ void ldm_x4(uint32_t* r, uint32_t addr) {
    asm volatile("ldmatrix.sync.aligned.m8n8.x4.shared.b16 {%0,%1,%2,%3}, [%4];"
                 : "=r"(r[0]), "=r"(r[1]), "=r"(r[2]), "=r"(r[3]) : "r"(addr));
}
__device__ __forceinline__ void ldm_x2(uint32_t* r, uint32_t addr) {
    asm volatile("ldmatrix.sync.aligned.m8n8.x2.shared.b16 {%0,%1}, [%2];"
                 : "=r"(r[0]), "=r"(r[1]) : "r"(addr));
}
__device__ __forceinline__ void ldm_x4_trans(uint32_t* r, uint32_t addr) {
    asm volatile("ldmatrix.sync.aligned.m8n8.x4.trans.shared.b16 {%0,%1,%2,%3}, [%4];"
                 : "=r"(r[0]), "=r"(r[1]), "=r"(r[2]), "=r"(r[3]) : "r"(addr));
}
__device__ __forceinline__ void mma_bf16(float* c, const uint32_t* a, const uint32_t* b) {
    asm volatile(
        "mma.sync.aligned.m16n8k16.row.col.f32.bf16.bf16.f32 "
        "{%0,%1,%2,%3}, {%4,%5,%6,%7}, {%8,%9}, {%0,%1,%2,%3};"
        : "+f"(c[0]), "+f"(c[1]), "+f"(c[2]), "+f"(c[3])
        : "r"(a[0]), "r"(a[1]), "r"(a[2]), "r"(a[3]), "r"(b[0]), "r"(b[1]));
}

__device__ __forceinline__ void split2(float v, __nv_bfloat16& h, __nv_bfloat16& l) {
    h = __float2bfloat16(v);
    l = __float2bfloat16(v - __bfloat162float(h));
}

// ---------------------------------------------------------------------------
__global__ void init_invfreq_kernel() {
    int i = threadIdx.x;
    if (i < 64) g_invfreq[i] = (float)pow(10000.0, -(double)(2 * i) / 128.0);
}

// ---------------------------------------------------------------------------
// fp32 -> (bf16 hi, bf16 lo) split, float4-vectorized
// ---------------------------------------------------------------------------
__global__ __launch_bounds__(256)
void split_bf16_kernel(const float* __restrict__ s, __nv_bfloat16* __restrict__ hi,
                       __nv_bfloat16* __restrict__ lo, int n4) {
    int i = blockIdx.x * blockDim.x + threadIdx.x;
    if (i >= n4) return;
    float4 v = ((const float4*)s)[i];
    __nv_bfloat16 h0, h1, h2, h3, l0, l1, l2, l3;
    split2(v.x, h0, l0); split2(v.y, h1, l1);
    split2(v.z, h2, l2); split2(v.w, h3, l3);
    uint2 hp, lp;
    hp.x = (uint32_t)__bfloat16_as_ushort(h0) | ((uint32_t)__bfloat16_as_ushort(h1) << 16);
    hp.y = (uint32_t)__bfloat16_as_ushort(h2) | ((uint32_t)__bfloat16_as_ushort(h3) << 16);
    lp.x = (uint32_t)__bfloat16_as_ushort(l0) | ((uint32_t)__bfloat16_as_ushort(l1) << 16);
    lp.y = (uint32_t)__bfloat16_as_ushort(l2) | ((uint32_t)__bfloat16_as_ushort(l3) << 16);
    ((uint2*)hi)[i] = hp;
    ((uint2*)lo)[i] = lp;
}

// ---------------------------------------------------------------------------
// mma.sync split-bf16 GEMM (512 threads, 16 warps, warp tile 32x32)
//   C[M,Nc] = (Ahi+Alo)[M,K] * (Bhi+Blo)[Nc,K]^T  via 3 bf16 products
// ---------------------------------------------------------------------------
#define GSTRIDE 40                         // bf16 elements per smem row
#define TILE_BYTES (128 * GSTRIDE * 2)     // 10240
#define STAGE_BYTES (4 * TILE_BYTES)       // 40960
#define NSTAGE 3

__global__ __launch_bounds__(512, 1)
void mma_gemm3_kernel(const __nv_bfloat16* __restrict__ Ahi, const __nv_bfloat16* __restrict__ Alo,
                      const __nv_bfloat16* __restrict__ Bhi, const __nv_bfloat16* __restrict__ Blo,
                      float* __restrict__ C, int Nc, int K) {
    extern __shared__ char smem[];
    const uint32_t smem_b = smem_u32_of(smem);

    const int tid = threadIdx.x;
    const int wid = tid >> 5;
    const int lane = tid & 31;
    const int warp_m = wid & 3;        // 4 x 32 rows
    const int warp_n = wid >> 2;       // 4 x 32 cols
    const int m0 = blockIdx.y * 128;
    const int n0 = blockIdx.x * 128;

    const int NCH = K >> 5;

    // stage loader: 2048 16B chunks / 512 threads = 4 per thread
    auto load_stage = [&](int st, int kc) {
        const uint32_t sb = smem_b + st * STAGE_BYTES;
        const int k0 = kc * 32;
#pragma unroll
        for (int t = 0; t < 4; t++) {
            int idx = tid + t * 512;
            int tile = idx >> 9;
            int w = idx & 511;
            int r = w >> 2;
            int c = w & 3;
            const __nv_bfloat16* base =
                (tile == 0) ? Ahi : (tile == 1) ? Alo : (tile == 2) ? Bhi : Blo;
            int row0 = (tile < 2) ? m0 : n0;
            const __nv_bfloat16* src = base + (size_t)(row0 + r) * K + k0 + c * 8;
            uint32_t dst = sb + tile * TILE_BYTES + r * (GSTRIDE * 2) + c * 16;
            CP_ASYNC16(dst, src);
        }
        CP_COMMIT();
    };

    float acc[2][4][4];
#pragma unroll
    for (int i = 0; i < 2; i++)
#pragma unroll
        for (int j = 0; j < 4; j++)
#pragma unroll
            for (int k = 0; k < 4; k++) acc[i][j][k] = 0.0f;

    load_stage(0, 0);
    load_stage(1, 1);

    const int a_row = warp_m * 32 + (lane & 15);
    const int a_cb  = (lane >> 4) * 8;
    const int b_row = warp_n * 32 + (lane & 7);
    const int b_cb  = ((lane >> 3) & 1) * 8;

    for (int cch = 0; cch < NCH; cch++) {
        int buf = cch % NSTAGE;
        if (cch + 2 < NCH) load_stage((cch + 2) % NSTAGE, cch + 2);
        else CP_COMMIT();
        CP_WAIT2();
        __syncthreads();

        const uint32_t sb = smem_b + buf * STAGE_BYTES;
        const uint32_t sAh = sb;
        const uint32_t sAl = sb + TILE_BYTES;
        const uint32_t sBh = sb + 2 * TILE_BYTES;
        const uint32_t sBl = sb + 3 * TILE_BYTES;

#pragma unroll
        for (int ks = 0; ks < 2; ks++) {
            const int kk = ks * 16;
            uint32_t ah[2][4], al[2][4], bh[4][2], bl[4][2];
#pragma unroll
            for (int mi = 0; mi < 2; mi++) {
                uint32_t off = (uint32_t)((a_row + mi * 16) * (GSTRIDE * 2) + (kk + a_cb) * 2);
                ldm_x4(ah[mi], sAh + off);
                ldm_x4(al[mi], sAl + off);
            }
#pragma unroll
            for (int ni = 0; ni < 4; ni++) {
                uint32_t off = (uint32_t)((b_row + ni * 8) * (GSTRIDE * 2) + (kk + b_cb) * 2);
                ldm_x2(bh[ni], sBh + off);
                ldm_x2(bl[ni], sBl + off);
            }
#pragma unroll
            for (int mi = 0; mi < 2; mi++)
#pragma unroll
                for (int ni = 0; ni < 4; ni++) {
                    mma_bf16(acc[mi][ni], ah[mi], bh[ni]);
                    mma_bf16(acc[mi][ni], ah[mi], bl[ni]);
                    mma_bf16(acc[mi][ni], al[mi], bh[ni]);
                }
        }
        __syncthreads();
    }

    const int er = lane >> 2;
    const int ec = (lane & 3) * 2;
#pragma unroll
    for (int mi = 0; mi < 2; mi++) {
#pragma unroll
        for (int ni = 0; ni < 4; ni++) {
            int gm = m0 + warp_m * 32 + mi * 16 + er;
            int gn = n0 + warp_n * 32 + ni * 8 + ec;
            *(float2*)(C + (size_t)gm * Nc + gn) = make_float2(acc[mi][ni][0], acc[mi][ni][1]);
            *(float2*)(C + (size_t)(gm + 8) * Nc + gn) = make_float2(acc[mi][ni][2], acc[mi][ni][3]);
        }
    }
}

// ---------------------------------------------------------------------------
// RMSNorm + RoPE, emitting bf16 hi/lo (Q pre-scaled by 1/sqrt(DH)).
// grid = (4096 tokens, 24 heads), 128 threads.
// ---------------------------------------------------------------------------
__global__ __launch_bounds__(128)
void normrope_kernel(const float* __restrict__ qkv, const int* __restrict__ pos,
                     const float* __restrict__ qw, const float* __restrict__ kw,
                     __nv_bfloat16* __restrict__ Qh, __nv_bfloat16* __restrict__ Ql,
                     __nv_bfloat16* __restrict__ Kh, __nv_bfloat16* __restrict__ Kl,
                     __nv_bfloat16* __restrict__ Vh, __nv_bfloat16* __restrict__ Vl) {
    int t = blockIdx.x;
    int hh = blockIdx.y;
    int d = threadIdx.x;
    int b = t >> 10;
    int n = t & 1023;

    float v = qkv[(size_t)t * EE + hh * DH + d];

    if (hh >= HQ + HKV) {
        size_t a = (((size_t)(b * HKV + hh - (HQ + HKV)) * NN + n) * DH) + d;
        __nv_bfloat16 h, l;
        split2(v, h, l);
        Vh[a] = h; Vl[a] = l;
        return;
    }

    __shared__ float s[128];
    __shared__ float red[4];

    float sq = v * v;
#pragma unroll
    for (int o = 16; o > 0; o >>= 1) sq += __shfl_xor_sync(0xFFFFFFFFu, sq, o);
    if ((d & 31) == 0) red[d >> 5] = sq;
    __syncthreads();
    float ms = (red[0] + red[1] + red[2] + red[3]) * (1.0f / 128.0f);
    float r = rsqrtf(ms + 1.1920929e-7f);
    float w = (hh < HQ) ? qw[d] : kw[d];
    s[d] = v * r * w;
    __syncthreads();

    float p = (float)pos[n];
    int f = (d < 64) ? d : d - 64;
    float ang = p * g_invfreq[f];
    float c, sn;
    sincosf(ang, &sn, &c);
    float out;
    if (d < 64) out = s[d] * c - s[d + 64] * sn;
    else        out = s[d] * c + s[d - 64] * sn;

    __nv_bfloat16 h, l;
    if (hh < HQ) {
        out *= 0.08838834764831845f;   // fold in attention scale
        split2(out, h, l);
        size_t a = (((size_t)(b * HQ + hh) * NN + n) * DH) + d;
        Qh[a] = h; Ql[a] = l;
    } else {
        split2(out, h, l);
        size_t a = (((size_t)(b * HKV + hh - HQ) * NN + n) * DH) + d;
        Kh[a] = h; Kl[a] = l;
    }
}

// ---------------------------------------------------------------------------
// Flash attention with mma.sync (split-bf16 QK^T and PV), causal.
// 64 queries x 64 keys per tile, 256 threads (8 warps, 2x4 layout).
// ---------------------------------------------------------------------------
#define QSTR 136     // bf16 row stride for Q/K/V tiles (272 B, conflict-free)
#define PSTR 72      // bf16 row stride for P (144 B)
#define SSTR 68      // fp32 row stride for S (272 B)

struct AttnSmem {
    __nv_bfloat16 Qh[64 * QSTR], Ql[64 * QSTR];
    __nv_bfloat16 Kh[64 * QSTR], Kl[64 * QSTR];
    __nv_bfloat16 Vh[64 * QSTR], Vl[64 * QSTR];
    float S[64 * SSTR];
    __nv_bfloat16 Ph[64 * PSTR], Pl[64 * PSTR];
    float row_alpha[64];
    float row_l[64];
};

__global__ __launch_bounds__(256, 1)
void attn_mma_kernel(const __nv_bfloat16* __restrict__ Qhg, const __nv_bfloat16* __restrict__ Qlg,
                     const __nv_bfloat16* __restrict__ Khg, const __nv_bfloat16* __restrict__ Klg,
                     const __nv_bfloat16* __restrict__ Vhg, const __nv_bfloat16* __restrict__ Vlg,
                     __nv_bfloat16* __restrict__ Yh, __nv_bfloat16* __restrict__ Yl) {
    extern __shared__ char smraw[];
    AttnSmem& sm = *(AttnSmem*)smraw;

    const int tid = threadIdx.x;
    const int wid = tid >> 5;
    const int lane = tid & 31;
    const int qt = blockIdx.x;
    const int h  = blockIdx.y;
    const int b  = blockIdx.z;
    const int q0 = qt * 64;
    const int hk = h >> 2;

    const size_t qbase = (((size_t)(b * HQ + h) * NN + q0) * DH);
    const size_t kbase = (((size_t)(b * HKV + hk) * NN) * DH);

    const uint32_t sQh = smem_u32_of(sm.Qh), sQl = smem_u32_of(sm.Ql);
    const uint32_t sKh = smem_u32_of(sm.Kh), sKl = smem_u32_of(sm.Kl);
    const uint32_t sVh = smem_u32_of(sm.Vh), sVl = smem_u32_of(sm.Vl);
    const uint32_t sPh = smem_u32_of(sm.Ph), sPl = smem_u32_of(sm.Pl);

    // ---- load Q tiles (64 x 128 bf16 each = 1024 uint4)
#pragma unroll
    for (int i = 0; i < 4; i++) {
        int idx = tid + i * 256;
        int row = idx >> 4, c = idx & 15;
        *(uint4*)&sm.Qh[row * QSTR + c * 8] = *(const uint4*)(Qhg + qbase + (size_t)row * DH + c * 8);
        *(uint4*)&sm.Ql[row * QSTR + c * 8] = *(const uint4*)(Qlg + qbase + (size_t)row * DH + c * 8);
    }

    const int warp_m = wid & 1;   // 2 x 32 query rows
    const int warp_n = wid >> 1;  // 4 x (16 key cols for S / 32 dims for PV)

    // softmax mapping
    const int srow = tid >> 2;
    const int sseg = tid & 3;
    float m_run = -1.0e30f, l_run = 0.0f;

    float o[2][4][4];
#pragma unroll
    for (int i = 0; i < 2; i++)
#pragma unroll
        for (int j = 0; j < 4; j++)
#pragma unroll
            for (int k = 0; k < 4; k++) o[i][j][k] = 0.0f;

    const int a_row = warp_m * 32 + (lane & 15);
    const int a_cb  = (lane >> 4) * 8;
    const int bk_row = warp_n * 16 + (lane & 7);
    const int bk_cb  = ((lane >> 3) & 1) * 8;
    const int er = lane >> 2;
    const int ec = (lane & 3) * 2;

    for (int kt = 0; kt <= qt; kt++) {
        __syncthreads();   // protect K/V/S/P reuse
        // ---- load K,V tiles (4 x 1024 uint4 / 256 threads = 16 each)
        const __nv_bfloat16* kvb[4] = {Khg + kbase, Klg + kbase, Vhg + kbase, Vlg + kbase};
        uint32_t kvdst[4] = {sKh, sKl, sVh, sVl};
#pragma unroll
        for (int i = 0; i < 16; i++) {
            int idx = tid + i * 256;
            int tile = idx >> 10;
            int w = idx & 1023;
            int row = w >> 4, c = w & 15;
            uint4 v = *(const uint4*)(kvb[tile] + (size_t)(kt * 64 + row) * DH + c * 8);
            *(uint4*)(smraw + (kvdst[tile] - smem_u32_of(smraw)) + row * (QSTR * 2) + c * 16) = v;
        }
        __syncthreads();

        // ---- S = Q K^T (3-product split)
        float sacc[2][2][4];
#pragma unroll
        for (int i = 0; i < 2; i++)
#pragma unroll
            for (int j = 0; j < 2; j++)
#pragma unroll
                for (int k = 0; k < 4; k++) sacc[i][j][k] = 0.0f;

#pragma unroll
        for (int ks = 0; ks < 8; ks++) {
            const int kk = ks * 16;
            uint32_t qh2[2][4], ql2[2][4], kh2[2][2], kl2[2][2];
#pragma unroll
            for (int mi = 0; mi < 2; mi++) {
                uint32_t off = (uint32_t)((a_row + mi * 16) * (QSTR * 2) + (kk + a_cb) * 2);
                ldm_x4(qh2[mi], sQh + off);
                ldm_x4(ql2[mi], sQl + off);
            }
#pragma unroll
            for (int ni = 0; ni < 2; ni++) {
                uint32_t off = (uint32_t)((bk_row + ni * 8) * (QSTR * 2) + (kk + bk_cb) * 2);
                ldm_x2(kh2[ni], sKh + off);
                ldm_x2(kl2[ni], sKl + off);
            }
#pragma unroll
            for (int mi = 0; mi < 2; mi++)
#pragma unroll
                for (int ni = 0; ni < 2; ni++) {
                    mma_bf16(sacc[mi][ni], qh2[mi], kh2[ni]);
                    mma_bf16(sacc[mi][ni], qh2[mi], kl2[ni]);
                    mma_bf16(sacc[mi][ni], ql2[mi], kh2[ni]);
                }
        }
        // write S to smem
#pragma unroll
        for (int mi = 0; mi < 2; mi++)
#pragma unroll
            for (int ni = 0; ni < 2; ni++) {
                int row = warp_m * 32 + mi * 16 + er;
                int col = warp_n * 16 + ni * 8 + ec;
                *(float2*)&sm.S[row * SSTR + col] = make_float2(sacc[mi][ni][0], sacc[mi][ni][1]);
                *(float2*)&sm.S[(row + 8) * SSTR + col] = make_float2(sacc[mi][ni][2], sacc[mi][ni][3]);
            }
        __syncthreads();

        // ---- online softmax (each thread: 1 row x 16 cols; 4 threads/row)
        {
            float sv[16];
            float vmax = -1.0e30f;
            const bool diag = (kt == qt);
#pragma unroll
            for (int j = 0; j < 16; j++) {
                int c = sseg * 16 + j;
                float s = sm.S[srow * SSTR + c];
                if (diag && c > srow) s = -1.0e30f;
                sv[j] = s;
                vmax = fmaxf(vmax, s);
            }
            vmax = fmaxf(vmax, __shfl_xor_sync(0xFFFFFFFFu, vmax, 1));
            vmax = fmaxf(vmax, __shfl_xor_sync(0xFFFFFFFFu, vmax, 2));
            float mnew = fmaxf(m_run, vmax);
            float alpha = __expf(m_run - mnew);
            float lsum = 0.0f;
#pragma unroll
            for (int j = 0; j < 16; j++) {
                float p = __expf(sv[j] - mnew);
                lsum += p;
                __nv_bfloat16 ph, pl;
                split2(p, ph, pl);
                sm.Ph[srow * PSTR + sseg * 16 + j] = ph;
                sm.Pl[srow * PSTR + sseg * 16 + j] = pl;
            }
            lsum += __shfl_xor_sync(0xFFFFFFFFu, lsum, 1);
            lsum += __shfl_xor_sync(0xFFFFFFFFu, lsum, 2);
            l_run = l_run * alpha + lsum;
            m_run = mnew;
            if (sseg == 0) sm.row_alpha[srow] = alpha;
        }
        __syncthreads();

        // ---- rescale O
#pragma unroll
        for (int mi = 0; mi < 2; mi++) {
            float a1 = sm.row_alpha[warp_m * 32 + mi * 16 + er];
            float a2 = sm.row_alpha[warp_m * 32 + mi * 16 + er + 8];
#pragma unroll
            for (int nj = 0; nj < 4; nj++) {
                o[mi][nj][0] *= a1; o[mi][nj][1] *= a1;
                o[mi][nj][2] *= a2; o[mi][nj][3] *= a2;
            }
        }
        // ---- O += P V  (A = P from smem, B = V^T via ldmatrix.trans)
        const int p_row = warp_m * 32 + (lane & 15);
        const int p_cb  = (lane >> 4) * 8;
#pragma unroll
        for (int ks = 0; ks < 4; ks++) {
            const int kk = ks * 16;
            uint32_t ph2[2][4], pl2[2][4], vh2[2][4], vl2[2][4];
#pragma unroll
            for (int mi = 0; mi < 2; mi++) {
                uint32_t off = (uint32_t)((p_row + mi * 16) * (PSTR * 2) + (kk + p_cb) * 2);
                ldm_x4(ph2[mi], sPh + off);
                ldm_x4(pl2[mi], sPl + off);
            }
#pragma unroll
            for (int nb = 0; nb < 2; nb++) {
                int vrow = kk + (lane & 15);
                int vcol = warp_n * 32 + nb * 16 + ((lane >> 4) & 1) * 8;
                uint32_t off = (uint32_t)(vrow * (QSTR * 2) + vcol * 2);
                ldm_x4_trans(vh2[nb], sVh + off);
                ldm_x4_trans(vl2[nb], sVl + off);
            }
#pragma unroll
            for (int mi = 0; mi < 2; mi++)
#pragma unroll
                for (int nj = 0; nj < 4; nj++) {
                    const uint32_t* bh = &vh2[nj >> 1][(nj & 1) * 2];
                    const uint32_t* bl = &vl2[nj >> 1][(nj & 1) * 2];
                    mma_bf16(o[mi][nj], ph2[mi], bh);
                    mma_bf16(o[mi][nj], ph2[mi], bl);
                    mma_bf16(o[mi][nj], pl2[mi], bh);
                }
        }
    }

    if (sseg == 0) sm.row_l[srow] = l_run;
    __syncthreads();

    // ---- epilogue: split O to bf16 hi/lo and store
#pragma unroll
    for (int mi = 0; mi < 2; mi++) {
        int r1 = warp_m * 32 + mi * 16 + er;
        int r2 = r1 + 8;
        float inv1 = 1.0f / sm.row_l[r1];
        float inv2 = 1.0f / sm.row_l[r2];
#pragma unroll
        for (int nj = 0; nj < 4; nj++) {
            int col = warp_n * 32 + nj * 8 + ec;
            size_t a1 = ((size_t)(b * NN + q0 + r1)) * DD + h * DH + col;
            size_t a2 = ((size_t)(b * NN + q0 + r2)) * DD + h * DH + col;
            float v0 = o[mi][nj][0] * inv1, v1 = o[mi][nj][1] * inv1;
            float v2 = o[mi][nj][2] * inv2, v3 = o[mi][nj][3] * inv2;
            __nv_bfloat16 h0, l0, h1, l1;
            split2(v0, h0, l0); split2(v1, h1, l1);
            *(uint32_t*)(Yh + a1) = (uint32_t)__bfloat16_as_ushort(h0) |
                                    ((uint32_t)__bfloat16_as_ushort(h1) << 16);
            *(uint32_t*)(Yl + a1) = (uint32_t)__bfloat16_as_ushort(l0) |
                                    ((uint32_t)__bfloat16_as_ushort(l1) << 16);
            split2(v2, h0, l0); split2(v3, h1, l1);
            *(uint32_t*)(Yh + a2) = (uint32_t)__bfloat16_as_ushort(h0) |
                                    ((uint32_t)__bfloat16_as_ushort(h1) << 16);
            *(uint32_t*)(Yl + a2) = (uint32_t)__bfloat16_as_ushort(l0) |
                                    ((uint32_t)__bfloat16_as_ushort(l1) << 16);
        }
    }
}

// ---------------------------------------------------------------------------
// launch
// ---------------------------------------------------------------------------
extern "C" void kernel_launch(void* const* d_in, const int* in_sizes, int n_in,
                              void* d_out, int out_size) {
    const float* x     = (const float*)d_in[0];
    const int*   pos   = (const int*)d_in[2];
    const float* w_qkv = (const float*)d_in[3];
    const float* w_out = (const float*)d_in[4];
    const float* qw    = (const float*)d_in[5];
    const float* kw    = (const float*)d_in[6];
    float* out = (float*)d_out;

    float* qkv;
    cudaGetSymbolAddress((void**)&qkv, g_qkv);
    __nv_bfloat16 *xh, *xl, *wqh, *wql, *woh, *wol, *yh, *yl;
    __nv_bfloat16 *qh, *ql, *kh, *kl, *vh, *vl;
    cudaGetSymbolAddress((void**)&xh,  g_xh);
    cudaGetSymbolAddress((void**)&xl,  g_xl);
    cudaGetSymbolAddress((void**)&wqh, g_wqh);
    cudaGetSymbolAddress((void**)&wql, g_wql);
    cudaGetSymbolAddress((void**)&woh, g_woh);
    cudaGetSymbolAddress((void**)&wol, g_wol);
    cudaGetSymbolAddress((void**)&yh,  g_yh);
    cudaGetSymbolAddress((void**)&yl,  g_yl);
    cudaGetSymbolAddress((void**)&qh,  g_qh);
    cudaGetSymbolAddress((void**)&ql,  g_ql);
    cudaGetSymbolAddress((void**)&kh,  g_kh);
    cudaGetSymbolAddress((void**)&kl,  g_kl);
    cudaGetSymbolAddress((void**)&vh,  g_vh);
    cudaGetSymbolAddress((void**)&vl,  g_vl);

    cudaFuncSetAttribute(mma_gemm3_kernel, cudaFuncAttributeMaxDynamicSharedMemorySize,
                         NSTAGE * STAGE_BYTES);
    cudaFuncSetAttribute(attn_mma_kernel, cudaFuncAttributeMaxDynamicSharedMemorySize,
                         (int)sizeof(AttnSmem));

    init_invfreq_kernel<<<1, 64>>>();

    split_bf16_kernel<<<(MTOK * DD / 4 + 255) / 256, 256>>>(x, xh, xl, MTOK * DD / 4);
    split_bf16_kernel<<<(EE * DD / 4 + 255) / 256, 256>>>(w_qkv, wqh, wql, EE * DD / 4);

    // QKV GEMM
    mma_gemm3_kernel<<<dim3(EE / 128, MTOK / 128), 512, NSTAGE * STAGE_BYTES>>>(
        xh, xl, wqh, wql, qkv, EE, DD);

    // RMSNorm + RoPE + split to bf16 hi/lo
    normrope_kernel<<<dim3(MTOK, HQ + 2 * HKV), 128>>>(qkv, pos, qw, kw,
                                                       qh, ql, kh, kl, vh, vl);

    // Attention (tensor-core flash, split-bf16)
    attn_mma_kernel<<<dim3(NN / 64, HQ, BB), 256, sizeof(AttnSmem)>>>(
        qh, ql, kh, kl, vh, vl, yh, yl);

    // Output GEMM
    split_bf16_kernel<<<(DD * DD / 4 + 255) / 256, 256>>>(w_out, woh, wol, DD * DD / 4);
    mma_gemm3_kernel<<<dim3(DD / 128, MTOK / 128), 512, NSTAGE * STAGE_BYTES>>>(
        yh, yl, woh, wol, out, DD, DD);
}

// round 9
// speedup vs baseline: 2.2240x; 1.0520x over previous
#include <cuda_runtime.h>
#include <cuda_bf16.h>
#include <math.h>
#include <stdint.h>

// Problem constants
#define BB 4
#define NN 1024
#define DD 2048
#define HQ 16
#define HKV 4
#define DH 128
#define EE 3072           // (HQ + 2*HKV) * DH
#define MTOK 4096         // B*N

// ---------------- scratch (device globals; no allocation allowed) ----------
__device__ float g_qkv[MTOK * EE];
__device__ float g_invfreq[64];

// bf16 split operands
__device__ __nv_bfloat16 g_xh[MTOK * DD],  g_xl[MTOK * DD];
__device__ __nv_bfloat16 g_wqh[EE * DD],   g_wql[EE * DD];
__device__ __nv_bfloat16 g_woh[DD * DD],   g_wol[DD * DD];
__device__ __nv_bfloat16 g_yh[MTOK * DD],  g_yl[MTOK * DD];
// attention operands (bf16 hi/lo, Q pre-scaled)
__device__ __nv_bfloat16 g_qh[BB * HQ * NN * DH],  g_ql[BB * HQ * NN * DH];
__device__ __nv_bfloat16 g_kh[BB * HKV * NN * DH], g_kl[BB * HKV * NN * DH];
__device__ __nv_bfloat16 g_vh[BB * HKV * NN * DH], g_vl[BB * HKV * NN * DH];

// ---------------------------------------------------------------------------
// portable PTX helpers (valid on plain sm_103 target)
// ---------------------------------------------------------------------------
__device__ __forceinline__ uint32_t smem_u32_of(const void* p) {
    uint32_t a;
    asm("{ .reg .u64 t; cvta.to.shared.u64 t, %1; cvt.u32.u64 %0, t; }"
        : "=r"(a) : "l"(p));
    return a;
}
#define CP_ASYNC16(dst, src) \
    asm volatile("cp.async.cg.shared.global [%0], [%1], 16;" :: "r"(dst), "l"(src))
#define CP_COMMIT() asm volatile("cp.async.commit_group;" ::: "memory")
#define CP_WAIT1()  asm volatile("cp.async.wait_group 1;" ::: "memory")

__device__ __forceinline__ void ldm_x4(uint32_t* r, uint32_t addr) {
    asm volatile("ldmatrix.sync.aligned.m8n8.x4.shared.b16 {%0,%1,%2,%3}, [%4];"
                 : "=r"(r[0]), "=r"(r[1]), "=r"(r[2]), "=r"(r[3]) : "r"(addr));
}
__device__ __forceinline__ void ldm_x4_trans(uint32_t* r, uint32_t addr) {
    asm volatile("ldmatrix.sync.aligned.m8n8.x4.trans.shared.b16 {%0,%1,%2,%3}, [%4];"
                 : "=r"(r[0]), "=r"(r[1]), "=r"(r[2]), "=r"(r[3]) : "r"(addr));
}
__device__ __forceinline__ void mma_bf16(float* c, const uint32_t* a, const uint32_t* b) {
    asm volatile(
        "mma.sync.aligned.m16n8k16.row.col.f32.bf16.bf16.f32 "
        "{%0,%1,%2,%3}, {%4,%5,%6,%7}, {%8,%9}, {%0,%1,%2,%3};"
        : "+f"(c[0]), "+f"(c[1]), "+f"(c[2]), "+f"(c[3])
        : "r"(a[0]), "r"(a[1]), "r"(a[2]), "r"(a[3]), "r"(b[0]), "r"(b[1]));
}

__device__ __forceinline__ void split2(float v, __nv_bfloat16& h, __nv_bfloat16& l) {
    h = __float2bfloat16(v);
    l = __float2bfloat16(v - __bfloat162float(h));
}

// ---------------------------------------------------------------------------
__global__ void init_invfreq_kernel() {
    int i = threadIdx.x;
    if (i < 64) g_invfreq[i] = (float)pow(10000.0, -(double)(2 * i) / 128.0);
}

// ---------------------------------------------------------------------------
// fp32 -> (bf16 hi, bf16 lo) split, float4-vectorized
// ---------------------------------------------------------------------------
__global__ __launch_bounds__(256)
void split_bf16_kernel(const float* __restrict__ s, __nv_bfloat16* __restrict__ hi,
                       __nv_bfloat16* __restrict__ lo, int n4) {
    int i = blockIdx.x * blockDim.x + threadIdx.x;
    if (i >= n4) return;
    float4 v = ((const float4*)s)[i];
    __nv_bfloat16 h0, h1, h2, h3, l0, l1, l2, l3;
    split2(v.x, h0, l0); split2(v.y, h1, l1);
    split2(v.z, h2, l2); split2(v.w, h3, l3);
    uint2 hp, lp;
    hp.x = (uint32_t)__bfloat16_as_ushort(h0) | ((uint32_t)__bfloat16_as_ushort(h1) << 16);
    hp.y = (uint32_t)__bfloat16_as_ushort(h2) | ((uint32_t)__bfloat16_as_ushort(h3) << 16);
    lp.x = (uint32_t)__bfloat16_as_ushort(l0) | ((uint32_t)__bfloat16_as_ushort(l1) << 16);
    lp.y = (uint32_t)__bfloat16_as_ushort(l2) | ((uint32_t)__bfloat16_as_ushort(l3) << 16);
    ((uint2*)hi)[i] = hp;
    ((uint2*)lo)[i] = lp;
}

// ---------------------------------------------------------------------------
// mma.sync split-bf16 GEMM (512 threads, 16 warps, warp tile 32x32)
// Single-barrier 3-stage pipeline: wait(1); sync; issue load(c+2); compute(c).
// ---------------------------------------------------------------------------
#define GSTRIDE 40                         // bf16 elements per smem row
#define TILE_BYTES (128 * GSTRIDE * 2)     // 10240
#define STAGE_BYTES (4 * TILE_BYTES)       // 40960
#define NSTAGE 3

__global__ __launch_bounds__(512, 1)
void mma_gemm3_kernel(const __nv_bfloat16* __restrict__ Ahi, const __nv_bfloat16* __restrict__ Alo,
                      const __nv_bfloat16* __restrict__ Bhi, const __nv_bfloat16* __restrict__ Blo,
                      float* __restrict__ C, int Nc, int K) {
    extern __shared__ char smem[];
    const uint32_t smem_b = smem_u32_of(smem);

    const int tid = threadIdx.x;
    const int wid = tid >> 5;
    const int lane = tid & 31;
    const int warp_m = wid & 3;        // 4 x 32 rows
    const int warp_n = wid >> 2;       // 4 x 32 cols
    const int m0 = blockIdx.y * 128;
    const int n0 = blockIdx.x * 128;

    const int NCH = K >> 5;

    // stage loader: 2048 16B chunks / 512 threads = 4 per thread
    auto load_stage = [&](int st, int kc) {
        const uint32_t sb = smem_b + st * STAGE_BYTES;
        const int k0 = kc * 32;
#pragma unroll
        for (int t = 0; t < 4; t++) {
            int idx = tid + t * 512;
            int tile = idx >> 9;
            int w = idx & 511;
            int r = w >> 2;
            int c = w & 3;
            const __nv_bfloat16* base =
                (tile == 0) ? Ahi : (tile == 1) ? Alo : (tile == 2) ? Bhi : Blo;
            int row0 = (tile < 2) ? m0 : n0;
            const __nv_bfloat16* src = base + (size_t)(row0 + r) * K + k0 + c * 8;
            uint32_t dst = sb + tile * TILE_BYTES + r * (GSTRIDE * 2) + c * 16;
            CP_ASYNC16(dst, src);
        }
        CP_COMMIT();
    };

    float acc[2][4][4];
#pragma unroll
    for (int i = 0; i < 2; i++)
#pragma unroll
        for (int j = 0; j < 4; j++)
#pragma unroll
            for (int k = 0; k < 4; k++) acc[i][j][k] = 0.0f;

    load_stage(0, 0);
    load_stage(1, 1);

    // fragment addressing
    const int a_row = warp_m * 32 + (lane & 15);
    const int a_cb  = (lane >> 4) * 8;
    // B x4: matrices 0,1 = n-block np*2, k halves; matrices 2,3 = n-block np*2+1
    const int b4_row = (lane & 7) + (((lane >> 3) >> 1) & 1) * 8;   // + np*16 + warp_n*32
    const int b4_cb  = ((lane >> 3) & 1) * 8;

    for (int cch = 0; cch < NCH; cch++) {
        CP_WAIT1();          // group cch complete (FIFO: {cch, cch+1} in flight)
        __syncthreads();     // all warps done with compute(cch-1)
        if (cch + 2 < NCH) load_stage((cch + 2) % NSTAGE, cch + 2);
        else CP_COMMIT();    // keep group count uniform

        const int buf = cch % NSTAGE;
        const uint32_t sb = smem_b + buf * STAGE_BYTES;
        const uint32_t sAh = sb;
        const uint32_t sAl = sb + TILE_BYTES;
        const uint32_t sBh = sb + 2 * TILE_BYTES;
        const uint32_t sBl = sb + 3 * TILE_BYTES;

#pragma unroll
        for (int ks = 0; ks < 2; ks++) {
            const int kk = ks * 16;
            uint32_t ah[2][4], al[2][4], bhf[2][4], blf[2][4];
#pragma unroll
            for (int mi = 0; mi < 2; mi++) {
                uint32_t off = (uint32_t)((a_row + mi * 16) * (GSTRIDE * 2) + (kk + a_cb) * 2);
                ldm_x4(ah[mi], sAh + off);
                ldm_x4(al[mi], sAl + off);
            }
#pragma unroll
            for (int np = 0; np < 2; np++) {
                uint32_t off = (uint32_t)((warp_n * 32 + np * 16 + b4_row) * (GSTRIDE * 2) +
                                          (kk + b4_cb) * 2);
                ldm_x4(bhf[np], sBh + off);
                ldm_x4(blf[np], sBl + off);
            }
#pragma unroll
            for (int mi = 0; mi < 2; mi++)
#pragma unroll
                for (int ni = 0; ni < 4; ni++) {
                    const uint32_t* bh = &bhf[ni >> 1][(ni & 1) * 2];
                    const uint32_t* bl = &blf[ni >> 1][(ni & 1) * 2];
                    mma_bf16(acc[mi][ni], ah[mi], bh);
                    mma_bf16(acc[mi][ni], ah[mi], bl);
                    mma_bf16(acc[mi][ni], al[mi], bh);
                }
        }
    }

    const int er = lane >> 2;
    const int ec = (lane & 3) * 2;
#pragma unroll
    for (int mi = 0; mi < 2; mi++) {
#pragma unroll
        for (int ni = 0; ni < 4; ni++) {
            int gm = m0 + warp_m * 32 + mi * 16 + er;
            int gn = n0 + warp_n * 32 + ni * 8 + ec;
            *(float2*)(C + (size_t)gm * Nc + gn) = make_float2(acc[mi][ni][0], acc[mi][ni][1]);
            *(float2*)(C + (size_t)(gm + 8) * Nc + gn) = make_float2(acc[mi][ni][2], acc[mi][ni][3]);
        }
    }
}

// ---------------------------------------------------------------------------
// RMSNorm + RoPE, emitting bf16 hi/lo (Q pre-scaled by 1/sqrt(DH)).
// ---------------------------------------------------------------------------
__global__ __launch_bounds__(128)
void normrope_kernel(const float* __restrict__ qkv, const int* __restrict__ pos,
                     const float* __restrict__ qw, const float* __restrict__ kw,
                     __nv_bfloat16* __restrict__ Qh, __nv_bfloat16* __restrict__ Ql,
                     __nv_bfloat16* __restrict__ Kh, __nv_bfloat16* __restrict__ Kl,
                     __nv_bfloat16* __restrict__ Vh, __nv_bfloat16* __restrict__ Vl) {
    int t = blockIdx.x;
    int hh = blockIdx.y;
    int d = threadIdx.x;
    int b = t >> 10;
    int n = t & 1023;

    float v = qkv[(size_t)t * EE + hh * DH + d];

    if (hh >= HQ + HKV) {
        size_t a = (((size_t)(b * HKV + hh - (HQ + HKV)) * NN + n) * DH) + d;
        __nv_bfloat16 h, l;
        split2(v, h, l);
        Vh[a] = h; Vl[a] = l;
        return;
    }

    __shared__ float s[128];
    __shared__ float red[4];

    float sq = v * v;
#pragma unroll
    for (int o = 16; o > 0; o >>= 1) sq += __shfl_xor_sync(0xFFFFFFFFu, sq, o);
    if ((d & 31) == 0) red[d >> 5] = sq;
    __syncthreads();
    float ms = (red[0] + red[1] + red[2] + red[3]) * (1.0f / 128.0f);
    float r = rsqrtf(ms + 1.1920929e-7f);
    float w = (hh < HQ) ? qw[d] : kw[d];
    s[d] = v * r * w;
    __syncthreads();

    float p = (float)pos[n];
    int f = (d < 64) ? d : d - 64;
    float ang = p * g_invfreq[f];
    float c, sn;
    sincosf(ang, &sn, &c);
    float out;
    if (d < 64) out = s[d] * c - s[d + 64] * sn;
    else        out = s[d] * c + s[d - 64] * sn;

    __nv_bfloat16 h, l;
    if (hh < HQ) {
        out *= 0.08838834764831845f;
        split2(out, h, l);
        size_t a = (((size_t)(b * HQ + hh) * NN + n) * DH) + d;
        Qh[a] = h; Ql[a] = l;
    } else {
        split2(out, h, l);
        size_t a = (((size_t)(b * HKV + hh - HQ) * NN + n) * DH) + d;
        Kh[a] = h; Kl[a] = l;
    }
}

// ---------------------------------------------------------------------------
// Flash attention with mma.sync (split-bf16 QK^T and PV), causal.
// 64 queries x 64 keys per tile, 256 threads (8 warps, 2x4 layout).
// ---------------------------------------------------------------------------
#define QSTR 136     // bf16 row stride for Q/K/V tiles (272 B)
#define PSTR 72      // bf16 row stride for P (144 B)
#define SSTR 68      // fp32 row stride for S (272 B)

struct AttnSmem {
    __nv_bfloat16 Qh[64 * QSTR], Ql[64 * QSTR];
    __nv_bfloat16 Kh[64 * QSTR], Kl[64 * QSTR];
    __nv_bfloat16 Vh[64 * QSTR], Vl[64 * QSTR];
    float S[64 * SSTR];
    __nv_bfloat16 Ph[64 * PSTR], Pl[64 * PSTR];
    float row_alpha[64];
    float row_l[64];
};

__global__ __launch_bounds__(256, 1)
void attn_mma_kernel(const __nv_bfloat16* __restrict__ Qhg, const __nv_bfloat16* __restrict__ Qlg,
                     const __nv_bfloat16* __restrict__ Khg, const __nv_bfloat16* __restrict__ Klg,
                     const __nv_bfloat16* __restrict__ Vhg, const __nv_bfloat16* __restrict__ Vlg,
                     __nv_bfloat16* __restrict__ Yh, __nv_bfloat16* __restrict__ Yl) {
    extern __shared__ char smraw[];
    AttnSmem& sm = *(AttnSmem*)smraw;

    const int tid = threadIdx.x;
    const int wid = tid >> 5;
    const int lane = tid & 31;
    const int qt = blockIdx.x;
    const int h  = blockIdx.y;
    const int b  = blockIdx.z;
    const int q0 = qt * 64;
    const int hk = h >> 2;

    const size_t qbase = (((size_t)(b * HQ + h) * NN + q0) * DH);
    const size_t kbase = (((size_t)(b * HKV + hk) * NN) * DH);

    const uint32_t sQh = smem_u32_of(sm.Qh), sQl = smem_u32_of(sm.Ql);
    const uint32_t sKh = smem_u32_of(sm.Kh), sKl = smem_u32_of(sm.Kl);
    const uint32_t sVh = smem_u32_of(sm.Vh), sVl = smem_u32_of(sm.Vl);
    const uint32_t sPh = smem_u32_of(sm.Ph), sPl = smem_u32_of(sm.Pl);

#pragma unroll
    for (int i = 0; i < 4; i++) {
        int idx = tid + i * 256;
        int row = idx >> 4, c = idx & 15;
        *(uint4*)&sm.Qh[row * QSTR + c * 8] = *(const uint4*)(Qhg + qbase + (size_t)row * DH + c * 8);
        *(uint4*)&sm.Ql[row * QSTR + c * 8] = *(const uint4*)(Qlg + qbase + (size_t)row * DH + c * 8);
    }

    const int warp_m = wid & 1;   // 2 x 32 query rows
    const int warp_n = wid >> 1;  // 4 x (16 key cols for S / 32 dims for PV)

    const int srow = tid >> 2;
    const int sseg = tid & 3;
    float m_run = -1.0e30f, l_run = 0.0f;

    float o[2][4][4];
#pragma unroll
    for (int i = 0; i < 2; i++)
#pragma unroll
        for (int j = 0; j < 4; j++)
#pragma unroll
            for (int k = 0; k < 4; k++) o[i][j][k] = 0.0f;

    const int a_row = warp_m * 32 + (lane & 15);
    const int a_cb  = (lane >> 4) * 8;
    // K x4 fragment addressing (2 n-blocks of 8 per op)
    const int k4_row = (lane & 7) + (((lane >> 3) >> 1) & 1) * 8;
    const int k4_cb  = ((lane >> 3) & 1) * 8;
    const int er = lane >> 2;
    const int ec = (lane & 3) * 2;

    for (int kt = 0; kt <= qt; kt++) {
        __syncthreads();
        const __nv_bfloat16* kvb[4] = {Khg + kbase, Klg + kbase, Vhg + kbase, Vlg + kbase};
        uint32_t kvdst[4] = {sKh, sKl, sVh, sVl};
#pragma unroll
        for (int i = 0; i < 16; i++) {
            int idx = tid + i * 256;
            int tile = idx >> 10;
            int w = idx & 1023;
            int row = w >> 4, c = w & 15;
            uint4 v = *(const uint4*)(kvb[tile] + (size_t)(kt * 64 + row) * DH + c * 8);
            *(uint4*)(smraw + (kvdst[tile] - smem_u32_of(smraw)) + row * (QSTR * 2) + c * 16) = v;
        }
        __syncthreads();

        // ---- S = Q K^T (3-product split)
        float sacc[2][2][4];
#pragma unroll
        for (int i = 0; i < 2; i++)
#pragma unroll
            for (int j = 0; j < 2; j++)
#pragma unroll
                for (int k = 0; k < 4; k++) sacc[i][j][k] = 0.0f;

#pragma unroll
        for (int ks = 0; ks < 8; ks++) {
            const int kk = ks * 16;
            uint32_t qh2[2][4], ql2[2][4], khf[4], klf[4];
#pragma unroll
            for (int mi = 0; mi < 2; mi++) {
                uint32_t off = (uint32_t)((a_row + mi * 16) * (QSTR * 2) + (kk + a_cb) * 2);
                ldm_x4(qh2[mi], sQh + off);
                ldm_x4(ql2[mi], sQl + off);
            }
            {
                uint32_t off = (uint32_t)((warp_n * 16 + k4_row) * (QSTR * 2) + (kk + k4_cb) * 2);
                ldm_x4(khf, sKh + off);
                ldm_x4(klf, sKl + off);
            }
#pragma unroll
            for (int mi = 0; mi < 2; mi++)
#pragma unroll
                for (int ni = 0; ni < 2; ni++) {
                    const uint32_t* kh = &khf[ni * 2];
                    const uint32_t* kl = &klf[ni * 2];
                    mma_bf16(sacc[mi][ni], qh2[mi], kh);
                    mma_bf16(sacc[mi][ni], qh2[mi], kl);
                    mma_bf16(sacc[mi][ni], ql2[mi], kh);
                }
        }
#pragma unroll
        for (int mi = 0; mi < 2; mi++)
#pragma unroll
            for (int ni = 0; ni < 2; ni++) {
                int row = warp_m * 32 + mi * 16 + er;
                int col = warp_n * 16 + ni * 8 + ec;
                *(float2*)&sm.S[row * SSTR + col] = make_float2(sacc[mi][ni][0], sacc[mi][ni][1]);
                *(float2*)&sm.S[(row + 8) * SSTR + col] = make_float2(sacc[mi][ni][2], sacc[mi][ni][3]);
            }
        __syncthreads();

        // ---- online softmax (1 row x 16 cols per thread)
        {
            float sv[16];
            float vmax = -1.0e30f;
            const bool diag = (kt == qt);
#pragma unroll
            for (int j = 0; j < 16; j++) {
                int c = sseg * 16 + j;
                float s = sm.S[srow * SSTR + c];
                if (diag && c > srow) s = -1.0e30f;
                sv[j] = s;
                vmax = fmaxf(vmax, s);
            }
            vmax = fmaxf(vmax, __shfl_xor_sync(0xFFFFFFFFu, vmax, 1));
            vmax = fmaxf(vmax, __shfl_xor_sync(0xFFFFFFFFu, vmax, 2));
            float mnew = fmaxf(m_run, vmax);
            float alpha = __expf(m_run - mnew);
            float lsum = 0.0f;
#pragma unroll
            for (int j = 0; j < 16; j++) {
                float p = __expf(sv[j] - mnew);
                lsum += p;
                __nv_bfloat16 ph, pl;
                split2(p, ph, pl);
                sm.Ph[srow * PSTR + sseg * 16 + j] = ph;
                sm.Pl[srow * PSTR + sseg * 16 + j] = pl;
            }
            lsum += __shfl_xor_sync(0xFFFFFFFFu, lsum, 1);
            lsum += __shfl_xor_sync(0xFFFFFFFFu, lsum, 2);
            l_run = l_run * alpha + lsum;
            m_run = mnew;
            if (sseg == 0) sm.row_alpha[srow] = alpha;
        }
        __syncthreads();

        // ---- rescale O
#pragma unroll
        for (int mi = 0; mi < 2; mi++) {
            float a1 = sm.row_alpha[warp_m * 32 + mi * 16 + er];
            float a2 = sm.row_alpha[warp_m * 32 + mi * 16 + er + 8];
#pragma unroll
            for (int nj = 0; nj < 4; nj++) {
                o[mi][nj][0] *= a1; o[mi][nj][1] *= a1;
                o[mi][nj][2] *= a2; o[mi][nj][3] *= a2;
            }
        }
        // ---- O += P V
        const int p_row = warp_m * 32 + (lane & 15);
        const int p_cb  = (lane >> 4) * 8;
#pragma unroll
        for (int ks = 0; ks < 4; ks++) {
            const int kk = ks * 16;
            uint32_t ph2[2][4], pl2[2][4], vh2[2][4], vl2[2][4];
#pragma unroll
            for (int mi = 0; mi < 2; mi++) {
                uint32_t off = (uint32_t)((p_row + mi * 16) * (PSTR * 2) + (kk + p_cb) * 2);
                ldm_x4(ph2[mi], sPh + off);
                ldm_x4(pl2[mi], sPl + off);
            }
#pragma unroll
            for (int nb = 0; nb < 2; nb++) {
                int vrow = kk + (lane & 15);
                int vcol = warp_n * 32 + nb * 16 + ((lane >> 4) & 1) * 8;
                uint32_t off = (uint32_t)(vrow * (QSTR * 2) + vcol * 2);
                ldm_x4_trans(vh2[nb], sVh + off);
                ldm_x4_trans(vl2[nb], sVl + off);
            }
#pragma unroll
            for (int mi = 0; mi < 2; mi++)
#pragma unroll
                for (int nj = 0; nj < 4; nj++) {
                    const uint32_t* bh = &vh2[nj >> 1][(nj & 1) * 2];
                    const uint32_t* bl = &vl2[nj >> 1][(nj & 1) * 2];
                    mma_bf16(o[mi][nj], ph2[mi], bh);
                    mma_bf16(o[mi][nj], ph2[mi], bl);
                    mma_bf16(o[mi][nj], pl2[mi], bh);
                }
        }
    }

    if (sseg == 0) sm.row_l[srow] = l_run;
    __syncthreads();

    // ---- epilogue
#pragma unroll
    for (int mi = 0; mi < 2; mi++) {
        int r1 = warp_m * 32 + mi * 16 + er;
        int r2 = r1 + 8;
        float inv1 = 1.0f / sm.row_l[r1];
        float inv2 = 1.0f / sm.row_l[r2];
#pragma unroll
        for (int nj = 0; nj < 4; nj++) {
            int col = warp_n * 32 + nj * 8 + ec;
            size_t a1 = ((size_t)(b * NN + q0 + r1)) * DD + h * DH + col;
            size_t a2 = ((size_t)(b * NN + q0 + r2)) * DD + h * DH + col;
            float v0 = o[mi][nj][0] * inv1, v1 = o[mi][nj][1] * inv1;
            float v2 = o[mi][nj][2] * inv2, v3 = o[mi][nj][3] * inv2;
            __nv_bfloat16 h0, l0, h1, l1;
            split2(v0, h0, l0); split2(v1, h1, l1);
            *(uint32_t*)(Yh + a1) = (uint32_t)__bfloat16_as_ushort(h0) |
                                    ((uint32_t)__bfloat16_as_ushort(h1) << 16);
            *(uint32_t*)(Yl + a1) = (uint32_t)__bfloat16_as_ushort(l0) |
                                    ((uint32_t)__bfloat16_as_ushort(l1) << 16);
            split2(v2, h0, l0); split2(v3, h1, l1);
            *(uint32_t*)(Yh + a2) = (uint32_t)__bfloat16_as_ushort(h0) |
                                    ((uint32_t)__bfloat16_as_ushort(h1) << 16);
            *(uint32_t*)(Yl + a2) = (uint32_t)__bfloat16_as_ushort(l0) |
                                    ((uint32_t)__bfloat16_as_ushort(l1) << 16);
        }
    }
}

// ---------------------------------------------------------------------------
// launch
// ---------------------------------------------------------------------------
extern "C" void kernel_launch(void* const* d_in, const int* in_sizes, int n_in,
                              void* d_out, int out_size) {
    const float* x     = (const float*)d_in[0];
    const int*   pos   = (const int*)d_in[2];
    const float* w_qkv = (const float*)d_in[3];
    const float* w_out = (const float*)d_in[4];
    const float* qw    = (const float*)d_in[5];
    const float* kw    = (const float*)d_in[6];
    float* out = (float*)d_out;

    float* qkv;
    cudaGetSymbolAddress((void**)&qkv, g_qkv);
    __nv_bfloat16 *xh, *xl, *wqh, *wql, *woh, *wol, *yh, *yl;
    __nv_bfloat16 *qh, *ql, *kh, *kl, *vh, *vl;
    cudaGetSymbolAddress((void**)&xh,  g_xh);
    cudaGetSymbolAddress((void**)&xl,  g_xl);
    cudaGetSymbolAddress((void**)&wqh, g_wqh);
    cudaGetSymbolAddress((void**)&wql, g_wql);
    cudaGetSymbolAddress((void**)&woh, g_woh);
    cudaGetSymbolAddress((void**)&wol, g_wol);
    cudaGetSymbolAddress((void**)&yh,  g_yh);
    cudaGetSymbolAddress((void**)&yl,  g_yl);
    cudaGetSymbolAddress((void**)&qh,  g_qh);
    cudaGetSymbolAddress((void**)&ql,  g_ql);
    cudaGetSymbolAddress((void**)&kh,  g_kh);
    cudaGetSymbolAddress((void**)&kl,  g_kl);
    cudaGetSymbolAddress((void**)&vh,  g_vh);
    cudaGetSymbolAddress((void**)&vl,  g_vl);

    cudaFuncSetAttribute(mma_gemm3_kernel, cudaFuncAttributeMaxDynamicSharedMemorySize,
                         NSTAGE * STAGE_BYTES);
    cudaFuncSetAttribute(attn_mma_kernel, cudaFuncAttributeMaxDynamicSharedMemorySize,
                         (int)sizeof(AttnSmem));

    init_invfreq_kernel<<<1, 64>>>();

    split_bf16_kernel<<<(MTOK * DD / 4 + 255) / 256, 256>>>(x, xh, xl, MTOK * DD / 4);
    split_bf16_kernel<<<(EE * DD / 4 + 255) / 256, 256>>>(w_qkv, wqh, wql, EE * DD / 4);

    // QKV GEMM
    mma_gemm3_kernel<<<dim3(EE / 128, MTOK / 128), 512, NSTAGE * STAGE_BYTES>>>(
        xh, xl, wqh, wql, qkv, EE, DD);

    // RMSNorm + RoPE + split to bf16 hi/lo
    normrope_kernel<<<dim3(MTOK, HQ + 2 * HKV), 128>>>(qkv, pos, qw, kw,
                                                       qh, ql, kh, kl, vh, vl);

    // Attention (tensor-core flash, split-bf16)
    attn_mma_kernel<<<dim3(NN / 64, HQ, BB), 256, sizeof(AttnSmem)>>>(
        qh, ql, kh, kl, vh, vl, yh, yl);

    // Output GEMM
    split_bf16_kernel<<<(DD * DD / 4 + 255) / 256, 256>>>(w_out, woh, wol, DD * DD / 4);
    mma_gemm3_kernel<<<dim3(DD / 128, MTOK / 128), 512, NSTAGE * STAGE_BYTES>>>(
        yh, yl, woh, wol, out, DD, DD);
}

// round 10
// speedup vs baseline: 2.4172x; 1.0869x over previous
#include <cuda_runtime.h>
#include <cuda_bf16.h>
#include <math.h>
#include <stdint.h>

// Problem constants
#define BB 4
#define NN 1024
#define DD 2048
#define HQ 16
#define HKV 4
#define DH 128
#define EE 3072           // (HQ + 2*HKV) * DH
#define MTOK 4096         // B*N

// ---------------- scratch (device globals; no allocation allowed) ----------
__device__ float g_qkv[MTOK * EE];
__device__ float g_invfreq[64];

// bf16 split operands
__device__ __nv_bfloat16 g_xh[MTOK * DD],  g_xl[MTOK * DD];
__device__ __nv_bfloat16 g_wqh[EE * DD],   g_wql[EE * DD];
__device__ __nv_bfloat16 g_woh[DD * DD],   g_wol[DD * DD];
__device__ __nv_bfloat16 g_yh[MTOK * DD],  g_yl[MTOK * DD];
// attention operands (bf16 hi/lo, Q pre-scaled)
__device__ __nv_bfloat16 g_qh[BB * HQ * NN * DH],  g_ql[BB * HQ * NN * DH];
__device__ __nv_bfloat16 g_kh[BB * HKV * NN * DH], g_kl[BB * HKV * NN * DH];
__device__ __nv_bfloat16 g_vh[BB * HKV * NN * DH], g_vl[BB * HKV * NN * DH];

// ---------------------------------------------------------------------------
// portable PTX helpers (valid on plain sm_103 target)
// ---------------------------------------------------------------------------
__device__ __forceinline__ uint32_t smem_u32_of(const void* p) {
    uint32_t a;
    asm("{ .reg .u64 t; cvta.to.shared.u64 t, %1; cvt.u32.u64 %0, t; }"
        : "=r"(a) : "l"(p));
    return a;
}
#define CP_ASYNC16(dst, src) \
    asm volatile("cp.async.cg.shared.global [%0], [%1], 16;" :: "r"(dst), "l"(src))
#define CP_COMMIT() asm volatile("cp.async.commit_group;" ::: "memory")
#define CP_WAIT1()  asm volatile("cp.async.wait_group 1;" ::: "memory")

__device__ __forceinline__ void ldm_x4(uint32_t* r, uint32_t addr) {
    asm volatile("ldmatrix.sync.aligned.m8n8.x4.shared.b16 {%0,%1,%2,%3}, [%4];"
                 : "=r"(r[0]), "=r"(r[1]), "=r"(r[2]), "=r"(r[3]) : "r"(addr));
}
__device__ __forceinline__ void ldm_x4_trans(uint32_t* r, uint32_t addr) {
    asm volatile("ldmatrix.sync.aligned.m8n8.x4.trans.shared.b16 {%0,%1,%2,%3}, [%4];"
                 : "=r"(r[0]), "=r"(r[1]), "=r"(r[2]), "=r"(r[3]) : "r"(addr));
}
__device__ __forceinline__ void mma_bf16(float* c, const uint32_t* a, const uint32_t* b) {
    asm volatile(
        "mma.sync.aligned.m16n8k16.row.col.f32.bf16.bf16.f32 "
        "{%0,%1,%2,%3}, {%4,%5,%6,%7}, {%8,%9}, {%0,%1,%2,%3};"
        : "+f"(c[0]), "+f"(c[1]), "+f"(c[2]), "+f"(c[3])
        : "r"(a[0]), "r"(a[1]), "r"(a[2]), "r"(a[3]), "r"(b[0]), "r"(b[1]));
}

__device__ __forceinline__ void split2(float v, __nv_bfloat16& h, __nv_bfloat16& l) {
    h = __float2bfloat16(v);
    l = __float2bfloat16(v - __bfloat162float(h));
}

// ---------------------------------------------------------------------------
__global__ void init_invfreq_kernel() {
    int i = threadIdx.x;
    if (i < 64) g_invfreq[i] = (float)pow(10000.0, -(double)(2 * i) / 128.0);
}

// ---------------------------------------------------------------------------
// fp32 -> (bf16 hi, bf16 lo) split, float4-vectorized
// ---------------------------------------------------------------------------
__global__ __launch_bounds__(256)
void split_bf16_kernel(const float* __restrict__ s, __nv_bfloat16* __restrict__ hi,
                       __nv_bfloat16* __restrict__ lo, int n4) {
    int i = blockIdx.x * blockDim.x + threadIdx.x;
    if (i >= n4) return;
    float4 v = ((const float4*)s)[i];
    __nv_bfloat16 h0, h1, h2, h3, l0, l1, l2, l3;
    split2(v.x, h0, l0); split2(v.y, h1, l1);
    split2(v.z, h2, l2); split2(v.w, h3, l3);
    uint2 hp, lp;
    hp.x = (uint32_t)__bfloat16_as_ushort(h0) | ((uint32_t)__bfloat16_as_ushort(h1) << 16);
    hp.y = (uint32_t)__bfloat16_as_ushort(h2) | ((uint32_t)__bfloat16_as_ushort(h3) << 16);
    lp.x = (uint32_t)__bfloat16_as_ushort(l0) | ((uint32_t)__bfloat16_as_ushort(l1) << 16);
    lp.y = (uint32_t)__bfloat16_as_ushort(l2) | ((uint32_t)__bfloat16_as_ushort(l3) << 16);
    ((uint2*)hi)[i] = hp;
    ((uint2*)lo)[i] = lp;
}

// ---------------------------------------------------------------------------
// mma.sync split-bf16 GEMM (512 threads, 16 warps, warp tile 32x32)
// K-chunk 64, 3-stage pipeline, single barrier per chunk:
//   wait(1); sync; issue load(c+2); compute(c)   [4 independent ks steps]
// ---------------------------------------------------------------------------
#define KCHUNK 64
#define GSTRIDE 72                         // bf16 elements per smem row (144 B)
#define TILE_BYTES (128 * GSTRIDE * 2)     // 18432
#define STAGE_BYTES (4 * TILE_BYTES)       // 73728
#define NSTAGE 3                           // 216 KB total

__global__ __launch_bounds__(512, 1)
void mma_gemm3_kernel(const __nv_bfloat16* __restrict__ Ahi, const __nv_bfloat16* __restrict__ Alo,
                      const __nv_bfloat16* __restrict__ Bhi, const __nv_bfloat16* __restrict__ Blo,
                      float* __restrict__ C, int Nc, int K) {
    extern __shared__ char smem[];
    const uint32_t smem_b = smem_u32_of(smem);

    const int tid = threadIdx.x;
    const int wid = tid >> 5;
    const int lane = tid & 31;
    const int warp_m = wid & 3;        // 4 x 32 rows
    const int warp_n = wid >> 2;       // 4 x 32 cols
    const int m0 = blockIdx.y * 128;
    const int n0 = blockIdx.x * 128;

    const int NCH = K >> 6;            // chunks of 64

    // stage loader: 4 tiles x 128 rows x 8 chunks16B = 4096 / 512 thr = 8 per thread
    auto load_stage = [&](int st, int kc) {
        const uint32_t sb = smem_b + st * STAGE_BYTES;
        const int k0 = kc * KCHUNK;
#pragma unroll
        for (int t = 0; t < 8; t++) {
            int idx = tid + t * 512;           // 0..4095
            int tile = idx >> 10;              // 0..3
            int w = idx & 1023;
            int r = w >> 3;                    // 0..127
            int c = w & 7;                     // 16B chunk in row
            const __nv_bfloat16* base =
                (tile == 0) ? Ahi : (tile == 1) ? Alo : (tile == 2) ? Bhi : Blo;
            int row0 = (tile < 2) ? m0 : n0;
            const __nv_bfloat16* src = base + (size_t)(row0 + r) * K + k0 + c * 8;
            uint32_t dst = sb + tile * TILE_BYTES + r * (GSTRIDE * 2) + c * 16;
            CP_ASYNC16(dst, src);
        }
        CP_COMMIT();
    };

    float acc[2][4][4];
#pragma unroll
    for (int i = 0; i < 2; i++)
#pragma unroll
        for (int j = 0; j < 4; j++)
#pragma unroll
            for (int k = 0; k < 4; k++) acc[i][j][k] = 0.0f;

    load_stage(0, 0);
    load_stage(1, 1);

    // fragment addressing
    const int a_row = warp_m * 32 + (lane & 15);
    const int a_cb  = (lane >> 4) * 8;
    // B x4: matrices {0,1} = k halves of n-block 0, {2,3} = n-block 1
    const int b4_row = (lane & 7) + (((lane >> 3) >> 1) & 1) * 8;
    const int b4_cb  = ((lane >> 3) & 1) * 8;

    for (int cch = 0; cch < NCH; cch++) {
        CP_WAIT1();          // group cch complete ({cch+1} may be in flight)
        __syncthreads();     // all warps done with compute(cch-1)
        if (cch + 2 < NCH) load_stage((cch + 2) % NSTAGE, cch + 2);
        else CP_COMMIT();    // keep group count uniform

        const int buf = cch % NSTAGE;
        const uint32_t sb = smem_b + buf * STAGE_BYTES;
        const uint32_t sAh = sb;
        const uint32_t sAl = sb + TILE_BYTES;
        const uint32_t sBh = sb + 2 * TILE_BYTES;
        const uint32_t sBl = sb + 3 * TILE_BYTES;

#pragma unroll
        for (int ks = 0; ks < 4; ks++) {
            const int kk = ks * 16;
            uint32_t ah[2][4], al[2][4], bhf[2][4], blf[2][4];
#pragma unroll
            for (int mi = 0; mi < 2; mi++) {
                uint32_t off = (uint32_t)((a_row + mi * 16) * (GSTRIDE * 2) + (kk + a_cb) * 2);
                ldm_x4(ah[mi], sAh + off);
                ldm_x4(al[mi], sAl + off);
            }
#pragma unroll
            for (int np = 0; np < 2; np++) {
                uint32_t off = (uint32_t)((warp_n * 32 + np * 16 + b4_row) * (GSTRIDE * 2) +
                                          (kk + b4_cb) * 2);
                ldm_x4(bhf[np], sBh + off);
                ldm_x4(blf[np], sBl + off);
            }
#pragma unroll
            for (int mi = 0; mi < 2; mi++)
#pragma unroll
                for (int ni = 0; ni < 4; ni++) {
                    const uint32_t* bh = &bhf[ni >> 1][(ni & 1) * 2];
                    const uint32_t* bl = &blf[ni >> 1][(ni & 1) * 2];
                    mma_bf16(acc[mi][ni], ah[mi], bh);
                    mma_bf16(acc[mi][ni], ah[mi], bl);
                    mma_bf16(acc[mi][ni], al[mi], bh);
                }
        }
    }

    const int er = lane >> 2;
    const int ec = (lane & 3) * 2;
#pragma unroll
    for (int mi = 0; mi < 2; mi++) {
#pragma unroll
        for (int ni = 0; ni < 4; ni++) {
            int gm = m0 + warp_m * 32 + mi * 16 + er;
            int gn = n0 + warp_n * 32 + ni * 8 + ec;
            *(float2*)(C + (size_t)gm * Nc + gn) = make_float2(acc[mi][ni][0], acc[mi][ni][1]);
            *(float2*)(C + (size_t)(gm + 8) * Nc + gn) = make_float2(acc[mi][ni][2], acc[mi][ni][3]);
        }
    }
}

// ---------------------------------------------------------------------------
// RMSNorm + RoPE, emitting bf16 hi/lo (Q pre-scaled by 1/sqrt(DH)).
// ---------------------------------------------------------------------------
__global__ __launch_bounds__(128)
void normrope_kernel(const float* __restrict__ qkv, const int* __restrict__ pos,
                     const float* __restrict__ qw, const float* __restrict__ kw,
                     __nv_bfloat16* __restrict__ Qh, __nv_bfloat16* __restrict__ Ql,
                     __nv_bfloat16* __restrict__ Kh, __nv_bfloat16* __restrict__ Kl,
                     __nv_bfloat16* __restrict__ Vh, __nv_bfloat16* __restrict__ Vl) {
    int t = blockIdx.x;
    int hh = blockIdx.y;
    int d = threadIdx.x;
    int b = t >> 10;
    int n = t & 1023;

    float v = qkv[(size_t)t * EE + hh * DH + d];

    if (hh >= HQ + HKV) {
        size_t a = (((size_t)(b * HKV + hh - (HQ + HKV)) * NN + n) * DH) + d;
        __nv_bfloat16 h, l;
        split2(v, h, l);
        Vh[a] = h; Vl[a] = l;
        return;
    }

    __shared__ float s[128];
    __shared__ float red[4];

    float sq = v * v;
#pragma unroll
    for (int o = 16; o > 0; o >>= 1) sq += __shfl_xor_sync(0xFFFFFFFFu, sq, o);
    if ((d & 31) == 0) red[d >> 5] = sq;
    __syncthreads();
    float ms = (red[0] + red[1] + red[2] + red[3]) * (1.0f / 128.0f);
    float r = rsqrtf(ms + 1.1920929e-7f);
    float w = (hh < HQ) ? qw[d] : kw[d];
    s[d] = v * r * w;
    __syncthreads();

    float p = (float)pos[n];
    int f = (d < 64) ? d : d - 64;
    float ang = p * g_invfreq[f];
    float c, sn;
    sincosf(ang, &sn, &c);
    float out;
    if (d < 64) out = s[d] * c - s[d + 64] * sn;
    else        out = s[d] * c + s[d - 64] * sn;

    __nv_bfloat16 h, l;
    if (hh < HQ) {
        out *= 0.08838834764831845f;
        split2(out, h, l);
        size_t a = (((size_t)(b * HQ + hh) * NN + n) * DH) + d;
        Qh[a] = h; Ql[a] = l;
    } else {
        split2(out, h, l);
        size_t a = (((size_t)(b * HKV + hh - HQ) * NN + n) * DH) + d;
        Kh[a] = h; Kl[a] = l;
    }
}

// ---------------------------------------------------------------------------
// Flash attention with mma.sync (split-bf16 QK^T and PV), causal.
// 64 queries x 64 keys per tile, 256 threads (8 warps, 2x4 layout).
// ---------------------------------------------------------------------------
#define QSTR 136     // bf16 row stride for Q/K/V tiles (272 B)
#define PSTR 72      // bf16 row stride for P (144 B)
#define SSTR 68      // fp32 row stride for S (272 B)

struct AttnSmem {
    __nv_bfloat16 Qh[64 * QSTR], Ql[64 * QSTR];
    __nv_bfloat16 Kh[64 * QSTR], Kl[64 * QSTR];
    __nv_bfloat16 Vh[64 * QSTR], Vl[64 * QSTR];
    float S[64 * SSTR];
    __nv_bfloat16 Ph[64 * PSTR], Pl[64 * PSTR];
    float row_alpha[64];
    float row_l[64];
};

__global__ __launch_bounds__(256, 1)
void attn_mma_kernel(const __nv_bfloat16* __restrict__ Qhg, const __nv_bfloat16* __restrict__ Qlg,
                     const __nv_bfloat16* __restrict__ Khg, const __nv_bfloat16* __restrict__ Klg,
                     const __nv_bfloat16* __restrict__ Vhg, const __nv_bfloat16* __restrict__ Vlg,
                     __nv_bfloat16* __restrict__ Yh, __nv_bfloat16* __restrict__ Yl) {
    extern __shared__ char smraw[];
    AttnSmem& sm = *(AttnSmem*)smraw;

    const int tid = threadIdx.x;
    const int wid = tid >> 5;
    const int lane = tid & 31;
    const int qt = blockIdx.x;
    const int h  = blockIdx.y;
    const int b  = blockIdx.z;
    const int q0 = qt * 64;
    const int hk = h >> 2;

    const size_t qbase = (((size_t)(b * HQ + h) * NN + q0) * DH);
    const size_t kbase = (((size_t)(b * HKV + hk) * NN) * DH);

    const uint32_t sQh = smem_u32_of(sm.Qh), sQl = smem_u32_of(sm.Ql);
    const uint32_t sKh = smem_u32_of(sm.Kh), sKl = smem_u32_of(sm.Kl);
    const uint32_t sVh = smem_u32_of(sm.Vh), sVl = smem_u32_of(sm.Vl);
    const uint32_t sPh = smem_u32_of(sm.Ph), sPl = smem_u32_of(sm.Pl);

#pragma unroll
    for (int i = 0; i < 4; i++) {
        int idx = tid + i * 256;
        int row = idx >> 4, c = idx & 15;
        *(uint4*)&sm.Qh[row * QSTR + c * 8] = *(const uint4*)(Qhg + qbase + (size_t)row * DH + c * 8);
        *(uint4*)&sm.Ql[row * QSTR + c * 8] = *(const uint4*)(Qlg + qbase + (size_t)row * DH + c * 8);
    }

    const int warp_m = wid & 1;   // 2 x 32 query rows
    const int warp_n = wid >> 1;  // 4 x (16 key cols for S / 32 dims for PV)

    const int srow = tid >> 2;
    const int sseg = tid & 3;
    float m_run = -1.0e30f, l_run = 0.0f;

    float o[2][4][4];
#pragma unroll
    for (int i = 0; i < 2; i++)
#pragma unroll
        for (int j = 0; j < 4; j++)
#pragma unroll
            for (int k = 0; k < 4; k++) o[i][j][k] = 0.0f;

    const int a_row = warp_m * 32 + (lane & 15);
    const int a_cb  = (lane >> 4) * 8;
    const int k4_row = (lane & 7) + (((lane >> 3) >> 1) & 1) * 8;
    const int k4_cb  = ((lane >> 3) & 1) * 8;
    const int er = lane >> 2;
    const int ec = (lane & 3) * 2;

    for (int kt = 0; kt <= qt; kt++) {
        __syncthreads();
        const __nv_bfloat16* kvb[4] = {Khg + kbase, Klg + kbase, Vhg + kbase, Vlg + kbase};
        uint32_t kvdst[4] = {sKh, sKl, sVh, sVl};
#pragma unroll
        for (int i = 0; i < 16; i++) {
            int idx = tid + i * 256;
            int tile = idx >> 10;
            int w = idx & 1023;
            int row = w >> 4, c = w & 15;
            uint4 v = *(const uint4*)(kvb[tile] + (size_t)(kt * 64 + row) * DH + c * 8);
            *(uint4*)(smraw + (kvdst[tile] - smem_u32_of(smraw)) + row * (QSTR * 2) + c * 16) = v;
        }
        __syncthreads();

        // ---- S = Q K^T (3-product split)
        float sacc[2][2][4];
#pragma unroll
        for (int i = 0; i < 2; i++)
#pragma unroll
            for (int j = 0; j < 2; j++)
#pragma unroll
                for (int k = 0; k < 4; k++) sacc[i][j][k] = 0.0f;

#pragma unroll
        for (int ks = 0; ks < 8; ks++) {
            const int kk = ks * 16;
            uint32_t qh2[2][4], ql2[2][4], khf[4], klf[4];
#pragma unroll
            for (int mi = 0; mi < 2; mi++) {
                uint32_t off = (uint32_t)((a_row + mi * 16) * (QSTR * 2) + (kk + a_cb) * 2);
                ldm_x4(qh2[mi], sQh + off);
                ldm_x4(ql2[mi], sQl + off);
            }
            {
                uint32_t off = (uint32_t)((warp_n * 16 + k4_row) * (QSTR * 2) + (kk + k4_cb) * 2);
                ldm_x4(khf, sKh + off);
                ldm_x4(klf, sKl + off);
            }
#pragma unroll
            for (int mi = 0; mi < 2; mi++)
#pragma unroll
                for (int ni = 0; ni < 2; ni++) {
                    const uint32_t* kh = &khf[ni * 2];
                    const uint32_t* kl = &klf[ni * 2];
                    mma_bf16(sacc[mi][ni], qh2[mi], kh);
                    mma_bf16(sacc[mi][ni], qh2[mi], kl);
                    mma_bf16(sacc[mi][ni], ql2[mi], kh);
                }
        }
#pragma unroll
        for (int mi = 0; mi < 2; mi++)
#pragma unroll
            for (int ni = 0; ni < 2; ni++) {
                int row = warp_m * 32 + mi * 16 + er;
                int col = warp_n * 16 + ni * 8 + ec;
                *(float2*)&sm.S[row * SSTR + col] = make_float2(sacc[mi][ni][0], sacc[mi][ni][1]);
                *(float2*)&sm.S[(row + 8) * SSTR + col] = make_float2(sacc[mi][ni][2], sacc[mi][ni][3]);
            }
        __syncthreads();

        // ---- online softmax (1 row x 16 cols per thread)
        {
            float sv[16];
            float vmax = -1.0e30f;
            const bool diag = (kt == qt);
#pragma unroll
            for (int j = 0; j < 16; j++) {
                int c = sseg * 16 + j;
                float s = sm.S[srow * SSTR + c];
                if (diag && c > srow) s = -1.0e30f;
                sv[j] = s;
                vmax = fmaxf(vmax, s);
            }
            vmax = fmaxf(vmax, __shfl_xor_sync(0xFFFFFFFFu, vmax, 1));
            vmax = fmaxf(vmax, __shfl_xor_sync(0xFFFFFFFFu, vmax, 2));
            float mnew = fmaxf(m_run, vmax);
            float alpha = __expf(m_run - mnew);
            float lsum = 0.0f;
#pragma unroll
            for (int j = 0; j < 16; j++) {
                float p = __expf(sv[j] - mnew);
                lsum += p;
                __nv_bfloat16 ph, pl;
                split2(p, ph, pl);
                sm.Ph[srow * PSTR + sseg * 16 + j] = ph;
                sm.Pl[srow * PSTR + sseg * 16 + j] = pl;
            }
            lsum += __shfl_xor_sync(0xFFFFFFFFu, lsum, 1);
            lsum += __shfl_xor_sync(0xFFFFFFFFu, lsum, 2);
            l_run = l_run * alpha + lsum;
            m_run = mnew;
            if (sseg == 0) sm.row_alpha[srow] = alpha;
        }
        __syncthreads();

        // ---- rescale O
#pragma unroll
        for (int mi = 0; mi < 2; mi++) {
            float a1 = sm.row_alpha[warp_m * 32 + mi * 16 + er];
            float a2 = sm.row_alpha[warp_m * 32 + mi * 16 + er + 8];
#pragma unroll
            for (int nj = 0; nj < 4; nj++) {
                o[mi][nj][0] *= a1; o[mi][nj][1] *= a1;
                o[mi][nj][2] *= a2; o[mi][nj][3] *= a2;
            }
        }
        // ---- O += P V
        const int p_row = warp_m * 32 + (lane & 15);
        const int p_cb  = (lane >> 4) * 8;
#pragma unroll
        for (int ks = 0; ks < 4; ks++) {
            const int kk = ks * 16;
            uint32_t ph2[2][4], pl2[2][4], vh2[2][4], vl2[2][4];
#pragma unroll
            for (int mi = 0; mi < 2; mi++) {
                uint32_t off = (uint32_t)((p_row + mi * 16) * (PSTR * 2) + (kk + p_cb) * 2);
                ldm_x4(ph2[mi], sPh + off);
                ldm_x4(pl2[mi], sPl + off);
            }
#pragma unroll
            for (int nb = 0; nb < 2; nb++) {
                int vrow = kk + (lane & 15);
                int vcol = warp_n * 32 + nb * 16 + ((lane >> 4) & 1) * 8;
                uint32_t off = (uint32_t)(vrow * (QSTR * 2) + vcol * 2);
                ldm_x4_trans(vh2[nb], sVh + off);
                ldm_x4_trans(vl2[nb], sVl + off);
            }
#pragma unroll
            for (int mi = 0; mi < 2; mi++)
#pragma unroll
                for (int nj = 0; nj < 4; nj++) {
                    const uint32_t* bh = &vh2[nj >> 1][(nj & 1) * 2];
                    const uint32_t* bl = &vl2[nj >> 1][(nj & 1) * 2];
                    mma_bf16(o[mi][nj], ph2[mi], bh);
                    mma_bf16(o[mi][nj], ph2[mi], bl);
                    mma_bf16(o[mi][nj], pl2[mi], bh);
                }
        }
    }

    if (sseg == 0) sm.row_l[srow] = l_run;
    __syncthreads();

    // ---- epilogue
#pragma unroll
    for (int mi = 0; mi < 2; mi++) {
        int r1 = warp_m * 32 + mi * 16 + er;
        int r2 = r1 + 8;
        float inv1 = 1.0f / sm.row_l[r1];
        float inv2 = 1.0f / sm.row_l[r2];
#pragma unroll
        for (int nj = 0; nj < 4; nj++) {
            int col = warp_n * 32 + nj * 8 + ec;
            size_t a1 = ((size_t)(b * NN + q0 + r1)) * DD + h * DH + col;
            size_t a2 = ((size_t)(b * NN + q0 + r2)) * DD + h * DH + col;
            float v0 = o[mi][nj][0] * inv1, v1 = o[mi][nj][1] * inv1;
            float v2 = o[mi][nj][2] * inv2, v3 = o[mi][nj][3] * inv2;
            __nv_bfloat16 h0, l0, h1, l1;
            split2(v0, h0, l0); split2(v1, h1, l1);
            *(uint32_t*)(Yh + a1) = (uint32_t)__bfloat16_as_ushort(h0) |
                                    ((uint32_t)__bfloat16_as_ushort(h1) << 16);
            *(uint32_t*)(Yl + a1) = (uint32_t)__bfloat16_as_ushort(l0) |
                                    ((uint32_t)__bfloat16_as_ushort(l1) << 16);
            split2(v2, h0, l0); split2(v3, h1, l1);
            *(uint32_t*)(Yh + a2) = (uint32_t)__bfloat16_as_ushort(h0) |
                                    ((uint32_t)__bfloat16_as_ushort(h1) << 16);
            *(uint32_t*)(Yl + a2) = (uint32_t)__bfloat16_as_ushort(l0) |
                                    ((uint32_t)__bfloat16_as_ushort(l1) << 16);
        }
    }
}

// ---------------------------------------------------------------------------
// launch
// ---------------------------------------------------------------------------
extern "C" void kernel_launch(void* const* d_in, const int* in_sizes, int n_in,
                              void* d_out, int out_size) {
    const float* x     = (const float*)d_in[0];
    const int*   pos   = (const int*)d_in[2];
    const float* w_qkv = (const float*)d_in[3];
    const float* w_out = (const float*)d_in[4];
    const float* qw    = (const float*)d_in[5];
    const float* kw    = (const float*)d_in[6];
    float* out = (float*)d_out;

    float* qkv;
    cudaGetSymbolAddress((void**)&qkv, g_qkv);
    __nv_bfloat16 *xh, *xl, *wqh, *wql, *woh, *wol, *yh, *yl;
    __nv_bfloat16 *qh, *ql, *kh, *kl, *vh, *vl;
    cudaGetSymbolAddress((void**)&xh,  g_xh);
    cudaGetSymbolAddress((void**)&xl,  g_xl);
    cudaGetSymbolAddress((void**)&wqh, g_wqh);
    cudaGetSymbolAddress((void**)&wql, g_wql);
    cudaGetSymbolAddress((void**)&woh, g_woh);
    cudaGetSymbolAddress((void**)&wol, g_wol);
    cudaGetSymbolAddress((void**)&yh,  g_yh);
    cudaGetSymbolAddress((void**)&yl,  g_yl);
    cudaGetSymbolAddress((void**)&qh,  g_qh);
    cudaGetSymbolAddress((void**)&ql,  g_ql);
    cudaGetSymbolAddress((void**)&kh,  g_kh);
    cudaGetSymbolAddress((void**)&kl,  g_kl);
    cudaGetSymbolAddress((void**)&vh,  g_vh);
    cudaGetSymbolAddress((void**)&vl,  g_vl);

    cudaFuncSetAttribute(mma_gemm3_kernel, cudaFuncAttributeMaxDynamicSharedMemorySize,
                         NSTAGE * STAGE_BYTES);
    cudaFuncSetAttribute(attn_mma_kernel, cudaFuncAttributeMaxDynamicSharedMemorySize,
                         (int)sizeof(AttnSmem));

    init_invfreq_kernel<<<1, 64>>>();

    split_bf16_kernel<<<(MTOK * DD / 4 + 255) / 256, 256>>>(x, xh, xl, MTOK * DD / 4);
    split_bf16_kernel<<<(EE * DD / 4 + 255) / 256, 256>>>(w_qkv, wqh, wql, EE * DD / 4);

    // QKV GEMM
    mma_gemm3_kernel<<<dim3(EE / 128, MTOK / 128), 512, NSTAGE * STAGE_BYTES>>>(
        xh, xl, wqh, wql, qkv, EE, DD);

    // RMSNorm + RoPE + split to bf16 hi/lo
    normrope_kernel<<<dim3(MTOK, HQ + 2 * HKV), 128>>>(qkv, pos, qw, kw,
                                                       qh, ql, kh, kl, vh, vl);

    // Attention (tensor-core flash, split-bf16)
    attn_mma_kernel<<<dim3(NN / 64, HQ, BB), 256, sizeof(AttnSmem)>>>(
        qh, ql, kh, kl, vh, vl, yh, yl);

    // Output GEMM
    split_bf16_kernel<<<(DD * DD / 4 + 255) / 256, 256>>>(w_out, woh, wol, DD * DD / 4);
    mma_gemm3_kernel<<<dim3(DD / 128, MTOK / 128), 512, NSTAGE * STAGE_BYTES>>>(
        yh, yl, woh, wol, out, DD, DD);
}